// round 1
// baseline (speedup 1.0000x reference)
#include <cuda_runtime.h>
#include <cstddef>

// ---------------- problem constants ----------------
#define N0C 120000
#define N1C 30000
#define N2C 6000
#define E0C 480000
#define E1C 96000
#define DC  128
#define RC  8
#define NBC 4
#define KNODE (DC + RC*DC)   // 1152

// ---------------- device scratch (static, no allocs) ----------------
__device__ float g_h0[(size_t)N0C * DC];          // 61.4 MB
__device__ float g_acc0[(size_t)N1C * RC * DC];   // 122.9 MB
__device__ float g_deg0[N1C];
__device__ float g_h1[(size_t)N1C * DC];          // 15.4 MB
__device__ float g_acc1[(size_t)N2C * RC * DC];   // 24.6 MB
__device__ float g_deg1[N2C];
__device__ float g_h2[(size_t)N2C * DC];          // 3.1 MB
__device__ float g_W0[KNODE * DC];                // [root0 ; W0[r]] stacked, 1152x128
__device__ float g_W1[KNODE * DC];

// ---------------- zero fill ----------------
__global__ void zero4_kernel(float4* __restrict__ p, int n4) {
    int i = blockIdx.x * blockDim.x + threadIdx.x;
    if (i < n4) p[i] = make_float4(0.f, 0.f, 0.f, 0.f);
}

// ---------------- build stacked weights: rows [0,128)=root, rows [128+r*128+i] = sum_b comp[r,b]*basis[b,i,:] ----------------
__global__ void build_W_kernel(const float* __restrict__ root,
                               const float* __restrict__ basis,  // [NB,128,128]
                               const float* __restrict__ comp,   // [R,NB]
                               float* __restrict__ Wf) {
    int idx = blockIdx.x * blockDim.x + threadIdx.x;
    if (idx >= KNODE * DC) return;
    int k = idx >> 7;      // 0..1151
    int o = idx & 127;
    float v;
    if (k < DC) {
        v = root[k * DC + o];
    } else {
        int r = (k - DC) >> 7;
        int i = (k - DC) & 127;
        v = 0.f;
        #pragma unroll
        for (int b = 0; b < NBC; b++)
            v += comp[r * NBC + b] * basis[((size_t)b * DC + i) * DC + o];
    }
    Wf[idx] = v;
}

// ---------------- edge aggregation: acc[dst, etype, :] += h[src, :]; deg[dst] += 1 ----------------
__global__ void edge_kernel(const int* __restrict__ src, const int* __restrict__ dst,
                            const int* __restrict__ eid, const int* __restrict__ et_all,
                            const float* __restrict__ h,
                            float* __restrict__ acc, float* __restrict__ deg, int E) {
    int e = blockIdx.x * (blockDim.x >> 5) + (threadIdx.x >> 5);
    int lane = threadIdx.x & 31;
    if (e >= E) return;
    int s = src[e];
    int d = dst[e];
    int r = et_all[eid[e]];
    float4 v = *reinterpret_cast<const float4*>(h + (size_t)s * DC + lane * 4);
    float* a = acc + (size_t)d * (RC * DC) + r * DC + lane * 4;
    atomicAdd(a + 0, v.x);
    atomicAdd(a + 1, v.y);
    atomicAdd(a + 2, v.z);
    atomicAdd(a + 3, v.w);
    if (lane == 0) atomicAdd(deg + d, 1.0f);
}

// ---------------- fused GEMM (+bias, optional LN+ReLU / ReLU) ----------------
// C[M,128] = A'[M,K] @ W[K,128]
//  MODE_PRE : A' = A[M,128],    out = relu(C + bias)
//  MODE_NODE: A' = [A | ACC*(1/max(deg,1))], K=1152, out = relu(LN(C + bias; gamma,beta))
//  MODE_POST: A' = A[M,128],    out = C + bias
enum { MODE_PRE = 0, MODE_NODE = 1, MODE_POST = 2 };

template <int MODE>
__global__ __launch_bounds__(256, 2)
void gemm_fused(const float* __restrict__ A,
                const float* __restrict__ ACC,
                const float* __restrict__ DEG,
                const float* __restrict__ W,
                const float* __restrict__ bias,
                const float* __restrict__ gamma,
                const float* __restrict__ beta,
                float* __restrict__ out,
                int M, int K) {
    __shared__ float As[8][128];
    __shared__ float Bs[8][128];
    __shared__ float invd[128];

    const int t = threadIdx.x;
    const int mBase = blockIdx.x * 128;
    const int ty = t >> 4;   // 0..15
    const int tx = t & 15;   // 0..15

    if (MODE == MODE_NODE) {
        if (t < 128) {
            int g = mBase + t;
            float dg = (g < M) ? DEG[g] : 1.0f;
            invd[t] = 1.0f / fmaxf(dg, 1.0f);
        }
    }

    float c[8][8];
    #pragma unroll
    for (int i = 0; i < 8; i++)
        #pragma unroll
        for (int j = 0; j < 8; j++) c[i][j] = 0.f;

    const int arow = t >> 1;
    const int aseg = (t & 1) * 4;
    const int grow_a = mBase + arow;
    const int bk = t >> 5;
    const int bcol = (t & 31) * 4;

    for (int k0 = 0; k0 < K; k0 += 8) {
        __syncthreads();
        // ---- A tile: As[k][m] (transposed) ----
        float4 av = make_float4(0.f, 0.f, 0.f, 0.f);
        if (grow_a < M) {
            int kk = k0 + aseg;
            if (MODE != MODE_NODE || kk < DC) {
                av = *reinterpret_cast<const float4*>(A + (size_t)grow_a * DC + kk);
            } else {
                av = *reinterpret_cast<const float4*>(ACC + (size_t)grow_a * (RC * DC) + (kk - DC));
                float s = invd[arow];
                av.x *= s; av.y *= s; av.z *= s; av.w *= s;
            }
        }
        As[aseg + 0][arow] = av.x;
        As[aseg + 1][arow] = av.y;
        As[aseg + 2][arow] = av.z;
        As[aseg + 3][arow] = av.w;
        // ---- B tile ----
        *reinterpret_cast<float4*>(&Bs[bk][bcol]) =
            *reinterpret_cast<const float4*>(W + (size_t)(k0 + bk) * DC + bcol);
        __syncthreads();
        // ---- compute ----
        #pragma unroll
        for (int kk = 0; kk < 8; kk++) {
            float4 a0 = *reinterpret_cast<const float4*>(&As[kk][ty * 4]);
            float4 a1 = *reinterpret_cast<const float4*>(&As[kk][ty * 4 + 64]);
            float4 b0 = *reinterpret_cast<const float4*>(&Bs[kk][tx * 4]);
            float4 b1 = *reinterpret_cast<const float4*>(&Bs[kk][tx * 4 + 64]);
            float a[8] = {a0.x, a0.y, a0.z, a0.w, a1.x, a1.y, a1.z, a1.w};
            float b[8] = {b0.x, b0.y, b0.z, b0.w, b1.x, b1.y, b1.z, b1.w};
            #pragma unroll
            for (int i = 0; i < 8; i++)
                #pragma unroll
                for (int j = 0; j < 8; j++)
                    c[i][j] += a[i] * b[j];
        }
    }

    // ---- epilogue ----
    const int c0 = tx * 4;
    const int c1 = tx * 4 + 64;
    float bv[8], gv[8], bev[8];
    #pragma unroll
    for (int j = 0; j < 8; j++) {
        int col = (j < 4) ? (c0 + j) : (c1 + j - 4);
        bv[j] = bias[col];
        if (MODE == MODE_NODE) { gv[j] = gamma[col]; bev[j] = beta[col]; }
    }

    #pragma unroll
    for (int i = 0; i < 8; i++) {
        int grow = mBase + ty * 4 + ((i < 4) ? i : (64 + i - 4));
        float v[8];
        #pragma unroll
        for (int j = 0; j < 8; j++) v[j] = c[i][j] + bv[j];

        if (MODE == MODE_NODE) {
            float s1 = 0.f, s2 = 0.f;
            #pragma unroll
            for (int j = 0; j < 8; j++) { s1 += v[j]; s2 += v[j] * v[j]; }
            #pragma unroll
            for (int off = 8; off >= 1; off >>= 1) {
                s1 += __shfl_xor_sync(0xffffffffu, s1, off, 16);
                s2 += __shfl_xor_sync(0xffffffffu, s2, off, 16);
            }
            float mu = s1 * (1.f / 128.f);
            float var = s2 * (1.f / 128.f) - mu * mu;
            float rs = rsqrtf(var + 1e-5f);
            #pragma unroll
            for (int j = 0; j < 8; j++)
                v[j] = fmaxf((v[j] - mu) * rs * gv[j] + bev[j], 0.f);
        } else if (MODE == MODE_PRE) {
            #pragma unroll
            for (int j = 0; j < 8; j++) v[j] = fmaxf(v[j], 0.f);
        }

        if (grow < M) {
            float4 o0 = make_float4(v[0], v[1], v[2], v[3]);
            float4 o1 = make_float4(v[4], v[5], v[6], v[7]);
            *reinterpret_cast<float4*>(out + (size_t)grow * DC + c0) = o0;
            *reinterpret_cast<float4*>(out + (size_t)grow * DC + c1) = o1;
        }
    }
}

// ---------------- launch ----------------
extern "C" void kernel_launch(void* const* d_in, const int* in_sizes, int n_in,
                              void* d_out, int out_size) {
    const float* x     = (const float*)d_in[0];
    const int*   src0  = (const int*)d_in[1];
    const int*   dst0  = (const int*)d_in[2];
    const int*   eid0  = (const int*)d_in[3];
    const int*   src1  = (const int*)d_in[4];
    const int*   dst1  = (const int*)d_in[5];
    const int*   eid1  = (const int*)d_in[6];
    const int*   etall = (const int*)d_in[7];
    const float* preW  = (const float*)d_in[8];
    const float* preB  = (const float*)d_in[9];
    const float* basis0= (const float*)d_in[10];
    const float* comp0 = (const float*)d_in[11];
    const float* root0 = (const float*)d_in[12];
    const float* bias0 = (const float*)d_in[13];
    const float* g0    = (const float*)d_in[14];
    const float* be0   = (const float*)d_in[15];
    const float* basis1= (const float*)d_in[16];
    const float* comp1 = (const float*)d_in[17];
    const float* root1 = (const float*)d_in[18];
    const float* bias1 = (const float*)d_in[19];
    const float* g1    = (const float*)d_in[20];
    const float* be1   = (const float*)d_in[21];
    const float* postW = (const float*)d_in[22];
    const float* postB = (const float*)d_in[23];

    float *h0, *acc0, *deg0, *h1, *acc1, *deg1, *h2, *W0, *W1;
    cudaGetSymbolAddress((void**)&h0,   g_h0);
    cudaGetSymbolAddress((void**)&acc0, g_acc0);
    cudaGetSymbolAddress((void**)&deg0, g_deg0);
    cudaGetSymbolAddress((void**)&h1,   g_h1);
    cudaGetSymbolAddress((void**)&acc1, g_acc1);
    cudaGetSymbolAddress((void**)&deg1, g_deg1);
    cudaGetSymbolAddress((void**)&h2,   g_h2);
    cudaGetSymbolAddress((void**)&W0,   g_W0);
    cudaGetSymbolAddress((void**)&W1,   g_W1);

    // 1) zero accumulators & degrees
    {
        int n4;
        n4 = (N1C * RC * DC) / 4;
        zero4_kernel<<<(n4 + 255) / 256, 256>>>((float4*)acc0, n4);
        n4 = N1C / 4;
        zero4_kernel<<<(n4 + 255) / 256, 256>>>((float4*)deg0, n4);
        n4 = (N2C * RC * DC) / 4;
        zero4_kernel<<<(n4 + 255) / 256, 256>>>((float4*)acc1, n4);
        n4 = N2C / 4;
        zero4_kernel<<<(n4 + 255) / 256, 256>>>((float4*)deg1, n4);
    }

    // 2) fold basis/comp/root into stacked weights
    build_W_kernel<<<(KNODE * DC + 255) / 256, 256>>>(root0, basis0, comp0, W0);
    build_W_kernel<<<(KNODE * DC + 255) / 256, 256>>>(root1, basis1, comp1, W1);

    // 3) pre: h0 = relu(x @ preW + preB)
    gemm_fused<MODE_PRE><<<(N0C + 127) / 128, 256>>>(
        x, nullptr, nullptr, preW, preB, nullptr, nullptr, h0, N0C, DC);

    // 4) edge aggregation layer 0
    edge_kernel<<<(E0C + 7) / 8, 256>>>(src0, dst0, eid0, etall, h0, acc0, deg0, E0C);

    // 5) node update 0: h1 = relu(LN([h0 | acc0/deg0] @ W0 + bias0))
    gemm_fused<MODE_NODE><<<(N1C + 127) / 128, 256>>>(
        h0, acc0, deg0, W0, bias0, g0, be0, h1, N1C, KNODE);

    // 6) edge aggregation layer 1
    edge_kernel<<<(E1C + 7) / 8, 256>>>(src1, dst1, eid1, etall, h1, acc1, deg1, E1C);

    // 7) node update 1
    gemm_fused<MODE_NODE><<<(N2C + 127) / 128, 256>>>(
        h1, acc1, deg1, W1, bias1, g1, be1, h2, N2C, KNODE);

    // 8) post: out = h2 @ postW + postB
    gemm_fused<MODE_POST><<<(N2C + 127) / 128, 256>>>(
        h2, nullptr, nullptr, postW, postB, nullptr, nullptr, (float*)d_out, N2C, DC);
}

// round 3
// speedup vs baseline: 1.2616x; 1.2616x over previous
#include <cuda_runtime.h>
#include <cuda_bf16.h>
#include <mma.h>
#include <cstdint>
#include <cstddef>

using namespace nvcuda;

// ---------------- problem constants ----------------
#define N0C 120000
#define N1C 30000
#define N2C 6000
#define E0C 480000
#define E1C 96000
#define DC  128
#define RC  8
#define NBC 4
#define KNODE (DC + RC*DC)   // 1152

// ---------------- device scratch ----------------
__device__ float g_h0[(size_t)N0C * DC];
__device__ float g_acc0[(size_t)N1C * RC * DC];
__device__ float g_deg0[N1C];
__device__ float g_h1[(size_t)N1C * DC];
__device__ float g_acc1[(size_t)N2C * RC * DC];
__device__ float g_deg1[N2C];
__device__ float g_h2[(size_t)N2C * DC];

// Folded, hi/lo-split weights W[k][n], bf16 row-major
__device__ __nv_bfloat16 g_WPre_hi[DC * DC];
__device__ __nv_bfloat16 g_WPre_lo[DC * DC];
__device__ __nv_bfloat16 g_W0_hi[KNODE * DC];
__device__ __nv_bfloat16 g_W0_lo[KNODE * DC];
__device__ __nv_bfloat16 g_W1_hi[KNODE * DC];
__device__ __nv_bfloat16 g_W1_lo[KNODE * DC];
__device__ __nv_bfloat16 g_WPost_hi[DC * DC];
__device__ __nv_bfloat16 g_WPost_lo[DC * DC];

// ---------------- zero fill ----------------
__global__ void zero4_kernel(float4* __restrict__ p, int n4) {
    int i = blockIdx.x * blockDim.x + threadIdx.x;
    if (i < n4) p[i] = make_float4(0.f, 0.f, 0.f, 0.f);
}

// ---------------- weight fold + split ----------------
__global__ void build_W_plain(const float* __restrict__ W,
                              __nv_bfloat16* __restrict__ hi,
                              __nv_bfloat16* __restrict__ lo) {
    int idx = blockIdx.x * blockDim.x + threadIdx.x;
    if (idx >= DC * DC) return;
    float v = W[idx];
    __nv_bfloat16 h = __float2bfloat16(v);
    hi[idx] = h;
    lo[idx] = __float2bfloat16(v - __bfloat162float(h));
}

__global__ void build_W_node(const float* __restrict__ root,
                             const float* __restrict__ basis,  // [NB,128,128]
                             const float* __restrict__ comp,   // [R,NB]
                             __nv_bfloat16* __restrict__ hi,
                             __nv_bfloat16* __restrict__ lo) {
    int idx = blockIdx.x * blockDim.x + threadIdx.x;
    if (idx >= KNODE * DC) return;
    int k = idx >> 7, n = idx & 127;
    float v;
    if (k < DC) {
        v = root[k * DC + n];
    } else {
        int r = (k - DC) >> 7;
        int i = (k - DC) & 127;
        v = 0.f;
        #pragma unroll
        for (int b = 0; b < NBC; b++)
            v += comp[r * NBC + b] * basis[((size_t)b * DC + i) * DC + n];
    }
    __nv_bfloat16 h = __float2bfloat16(v);
    hi[idx] = h;
    lo[idx] = __float2bfloat16(v - __bfloat162float(h));
}

// ---------------- edge aggregation ----------------
__global__ void edge_kernel(const int* __restrict__ src, const int* __restrict__ dst,
                            const int* __restrict__ eid, const int* __restrict__ et_all,
                            const float* __restrict__ h,
                            float* __restrict__ acc, float* __restrict__ deg, int E) {
    int e = blockIdx.x * (blockDim.x >> 5) + (threadIdx.x >> 5);
    int lane = threadIdx.x & 31;
    if (e >= E) return;
    int s = src[e];
    int d = dst[e];
    int r = et_all[eid[e]];
    float4 v = *reinterpret_cast<const float4*>(h + (size_t)s * DC + lane * 4);
    float* a = acc + (size_t)d * (RC * DC) + r * DC + lane * 4;
    atomicAdd(a + 0, v.x);
    atomicAdd(a + 1, v.y);
    atomicAdd(a + 2, v.z);
    atomicAdd(a + 3, v.w);
    if (lane == 0) atomicAdd(deg + d, 1.0f);
}

// ---------------- tensor-core fused GEMM (wmma bf16 split-precision) ----------------
enum { MODE_PRE = 0, MODE_NODE = 1, MODE_POST = 2 };

#define LDA 72      // A smem row stride (bf16 elements), 128 rows
#define LDB 136     // B smem row stride (bf16 elements), 64 rows
#define LDCS 132    // C smem row stride (floats), 128 rows

// dynamic smem layout (bytes)
#define OFF_BIAS 0
#define OFF_G    512
#define OFF_BE   1024
#define OFF_INVD 1536
#define OFF_DATA 2048
#define OFF_AHI  (OFF_DATA)
#define OFF_ALO  (OFF_AHI + 128*LDA*2)      // +18432
#define OFF_BHI  (OFF_ALO + 128*LDA*2)
#define OFF_BLO  (OFF_BHI + 64*LDB*2)       // +17408
#define SMEM_TOT (OFF_BLO + 64*LDB*2)       // 2048 + 36864 + 34816 = 73728
#define OFF_C    (OFF_DATA)                 // reuse staging for C: 128*132*4 = 67584 <= 71680

template <int MODE>
__global__ __launch_bounds__(256)
void gemm_tc(const float* __restrict__ A,
             const float* __restrict__ ACC,
             const float* __restrict__ DEG,
             const __nv_bfloat16* __restrict__ W_hi,
             const __nv_bfloat16* __restrict__ W_lo,
             const float* __restrict__ bias,
             const float* __restrict__ gamma,
             const float* __restrict__ beta,
             float* __restrict__ out,
             int M, int K) {
    extern __shared__ char smem[];
    const int t = threadIdx.x;
    const int w = t >> 5;
    const int wm = w >> 1;       // 0..3  (M group of 32 rows)
    const int wn = w & 1;        // 0..1  (N group of 64 cols)
    const int mBase = blockIdx.x * 128;

    float* s_bias = (float*)(smem + OFF_BIAS);
    float* s_g    = (float*)(smem + OFF_G);
    float* s_be   = (float*)(smem + OFF_BE);
    float* s_invd = (float*)(smem + OFF_INVD);
    __nv_bfloat16* As_hi = (__nv_bfloat16*)(smem + OFF_AHI);
    __nv_bfloat16* As_lo = (__nv_bfloat16*)(smem + OFF_ALO);
    __nv_bfloat16* Bs_hi = (__nv_bfloat16*)(smem + OFF_BHI);
    __nv_bfloat16* Bs_lo = (__nv_bfloat16*)(smem + OFF_BLO);

    if (t < 128) {
        s_bias[t] = bias[t];
        if (MODE == MODE_NODE) {
            int g = mBase + t;
            float dg = (g < M) ? DEG[g] : 1.0f;
            s_invd[t] = 1.0f / fmaxf(dg, 1.0f);
            s_g[t]  = gamma[t];
            s_be[t] = beta[t];
        }
    }
    __syncthreads();

    wmma::fragment<wmma::accumulator, 16, 16, 16, float> acc[2][4];
    #pragma unroll
    for (int i = 0; i < 2; i++)
        #pragma unroll
        for (int j = 0; j < 4; j++)
            wmma::fill_fragment(acc[i][j], 0.f);

    const int nCh = K >> 6;
    for (int c = 0; c < nCh; c++) {
        const int k0 = c * 64;
        __syncthreads();
        // ---- A stage: 128 rows x 64 k fp32 -> hi/lo bf16 ----
        #pragma unroll
        for (int it = 0; it < 8; it++) {
            int v = it * 256 + t;     // 2048 float4
            int row = v >> 4;
            int seg = v & 15;
            int kk = k0 + seg * 4;
            int g = mBase + row;
            float4 av = make_float4(0.f, 0.f, 0.f, 0.f);
            if (g < M) {
                if (MODE != MODE_NODE || kk < DC) {
                    av = *reinterpret_cast<const float4*>(A + (size_t)g * DC + kk);
                } else {
                    av = *reinterpret_cast<const float4*>(ACC + (size_t)g * (RC * DC) + (kk - DC));
                    float s = s_invd[row];
                    av.x *= s; av.y *= s; av.z *= s; av.w *= s;
                }
            }
            __nv_bfloat162 h01 = __floats2bfloat162_rn(av.x, av.y);
            __nv_bfloat162 h23 = __floats2bfloat162_rn(av.z, av.w);
            float rx = av.x - __bfloat162float(__low2bfloat16(h01));
            float ry = av.y - __bfloat162float(__high2bfloat16(h01));
            float rz = av.z - __bfloat162float(__low2bfloat16(h23));
            float rw = av.w - __bfloat162float(__high2bfloat16(h23));
            __nv_bfloat162 l01 = __floats2bfloat162_rn(rx, ry);
            __nv_bfloat162 l23 = __floats2bfloat162_rn(rz, rw);
            uint2 hp, lp;
            hp.x = *(uint32_t*)&h01; hp.y = *(uint32_t*)&h23;
            lp.x = *(uint32_t*)&l01; lp.y = *(uint32_t*)&l23;
            int off = row * LDA + seg * 4;
            *reinterpret_cast<uint2*>(As_hi + off) = hp;
            *reinterpret_cast<uint2*>(As_lo + off) = lp;
        }
        // ---- B stage: 64 k x 128 n bf16 copy (hi+lo) ----
        #pragma unroll
        for (int it = 0; it < 4; it++) {
            int v = it * 256 + t;     // 1024 float4 = 8192 bf16
            int row = v >> 4;
            int col8 = (v & 15) * 8;
            const float4* srcH = reinterpret_cast<const float4*>(W_hi + (size_t)(k0 + row) * DC + col8);
            const float4* srcL = reinterpret_cast<const float4*>(W_lo + (size_t)(k0 + row) * DC + col8);
            *reinterpret_cast<float4*>(Bs_hi + row * LDB + col8) = *srcH;
            *reinterpret_cast<float4*>(Bs_lo + row * LDB + col8) = *srcL;
        }
        __syncthreads();
        // ---- compute: 4 k16 steps ----
        #pragma unroll
        for (int ks = 0; ks < 4; ks++) {
            wmma::fragment<wmma::matrix_a, 16, 16, 16, __nv_bfloat16, wmma::row_major> a_hi[2], a_lo[2];
            #pragma unroll
            for (int i = 0; i < 2; i++) {
                const __nv_bfloat16* ap = As_hi + (wm * 32 + i * 16) * LDA + ks * 16;
                wmma::load_matrix_sync(a_hi[i], ap, LDA);
                const __nv_bfloat16* alp = As_lo + (wm * 32 + i * 16) * LDA + ks * 16;
                wmma::load_matrix_sync(a_lo[i], alp, LDA);
            }
            #pragma unroll
            for (int j = 0; j < 4; j++) {
                wmma::fragment<wmma::matrix_b, 16, 16, 16, __nv_bfloat16, wmma::row_major> b_hi, b_lo;
                const __nv_bfloat16* bp = Bs_hi + (ks * 16) * LDB + wn * 64 + j * 16;
                wmma::load_matrix_sync(b_hi, bp, LDB);
                const __nv_bfloat16* blp = Bs_lo + (ks * 16) * LDB + wn * 64 + j * 16;
                wmma::load_matrix_sync(b_lo, blp, LDB);
                #pragma unroll
                for (int i = 0; i < 2; i++) {
                    wmma::mma_sync(acc[i][j], a_hi[i], b_hi, acc[i][j]);
                    wmma::mma_sync(acc[i][j], a_hi[i], b_lo, acc[i][j]);
                    wmma::mma_sync(acc[i][j], a_lo[i], b_hi, acc[i][j]);
                }
            }
        }
    }

    // ---- write C to smem ----
    __syncthreads();
    float* Cs = (float*)(smem + OFF_C);
    #pragma unroll
    for (int i = 0; i < 2; i++)
        #pragma unroll
        for (int j = 0; j < 4; j++)
            wmma::store_matrix_sync(Cs + (wm * 32 + i * 16) * LDCS + wn * 64 + j * 16,
                                    acc[i][j], LDCS, wmma::mem_row_major);
    __syncthreads();

    // ---- epilogue: 2 threads per row ----
    {
        int row = t >> 1;
        int half = t & 1;
        int grow = mBase + row;
        const float* crow = Cs + row * LDCS + half * 64;
        float v[64];
        #pragma unroll
        for (int q = 0; q < 16; q++) {
            float4 cv = *reinterpret_cast<const float4*>(crow + q * 4);
            v[q * 4 + 0] = cv.x + s_bias[half * 64 + q * 4 + 0];
            v[q * 4 + 1] = cv.y + s_bias[half * 64 + q * 4 + 1];
            v[q * 4 + 2] = cv.z + s_bias[half * 64 + q * 4 + 2];
            v[q * 4 + 3] = cv.w + s_bias[half * 64 + q * 4 + 3];
        }
        if (MODE == MODE_NODE) {
            float s1 = 0.f, s2 = 0.f;
            #pragma unroll
            for (int j = 0; j < 64; j++) { s1 += v[j]; s2 += v[j] * v[j]; }
            s1 += __shfl_xor_sync(0xffffffffu, s1, 1);
            s2 += __shfl_xor_sync(0xffffffffu, s2, 1);
            float mu = s1 * (1.f / 128.f);
            float var = s2 * (1.f / 128.f) - mu * mu;
            float rs = rsqrtf(var + 1e-5f);
            #pragma unroll
            for (int j = 0; j < 64; j++)
                v[j] = fmaxf((v[j] - mu) * rs * s_g[half * 64 + j] + s_be[half * 64 + j], 0.f);
        } else if (MODE == MODE_PRE) {
            #pragma unroll
            for (int j = 0; j < 64; j++) v[j] = fmaxf(v[j], 0.f);
        }
        if (grow < M) {
            #pragma unroll
            for (int q = 0; q < 16; q++) {
                float4 o = make_float4(v[q * 4], v[q * 4 + 1], v[q * 4 + 2], v[q * 4 + 3]);
                *reinterpret_cast<float4*>(out + (size_t)grow * DC + half * 64 + q * 4) = o;
            }
        }
    }
}

// ---------------- launch ----------------
extern "C" void kernel_launch(void* const* d_in, const int* in_sizes, int n_in,
                              void* d_out, int out_size) {
    const float* x     = (const float*)d_in[0];
    const int*   src0  = (const int*)d_in[1];
    const int*   dst0  = (const int*)d_in[2];
    const int*   eid0  = (const int*)d_in[3];
    const int*   src1  = (const int*)d_in[4];
    const int*   dst1  = (const int*)d_in[5];
    const int*   eid1  = (const int*)d_in[6];
    const int*   etall = (const int*)d_in[7];
    const float* preW  = (const float*)d_in[8];
    const float* preB  = (const float*)d_in[9];
    const float* basis0= (const float*)d_in[10];
    const float* comp0 = (const float*)d_in[11];
    const float* root0 = (const float*)d_in[12];
    const float* bias0 = (const float*)d_in[13];
    const float* g0    = (const float*)d_in[14];
    const float* be0   = (const float*)d_in[15];
    const float* basis1= (const float*)d_in[16];
    const float* comp1 = (const float*)d_in[17];
    const float* root1 = (const float*)d_in[18];
    const float* bias1 = (const float*)d_in[19];
    const float* g1    = (const float*)d_in[20];
    const float* be1   = (const float*)d_in[21];
    const float* postW = (const float*)d_in[22];
    const float* postB = (const float*)d_in[23];

    float *h0, *acc0, *deg0, *h1, *acc1, *deg1, *h2;
    __nv_bfloat16 *wpreh, *wprel, *w0h, *w0l, *w1h, *w1l, *wposth, *wpostl;
    cudaGetSymbolAddress((void**)&h0,   g_h0);
    cudaGetSymbolAddress((void**)&acc0, g_acc0);
    cudaGetSymbolAddress((void**)&deg0, g_deg0);
    cudaGetSymbolAddress((void**)&h1,   g_h1);
    cudaGetSymbolAddress((void**)&acc1, g_acc1);
    cudaGetSymbolAddress((void**)&deg1, g_deg1);
    cudaGetSymbolAddress((void**)&h2,   g_h2);
    cudaGetSymbolAddress((void**)&wpreh, g_WPre_hi);
    cudaGetSymbolAddress((void**)&wprel, g_WPre_lo);
    cudaGetSymbolAddress((void**)&w0h,   g_W0_hi);
    cudaGetSymbolAddress((void**)&w0l,   g_W0_lo);
    cudaGetSymbolAddress((void**)&w1h,   g_W1_hi);
    cudaGetSymbolAddress((void**)&w1l,   g_W1_lo);
    cudaGetSymbolAddress((void**)&wposth, g_WPost_hi);
    cudaGetSymbolAddress((void**)&wpostl, g_WPost_lo);

    cudaFuncSetAttribute(gemm_tc<MODE_PRE>,  cudaFuncAttributeMaxDynamicSharedMemorySize, SMEM_TOT);
    cudaFuncSetAttribute(gemm_tc<MODE_NODE>, cudaFuncAttributeMaxDynamicSharedMemorySize, SMEM_TOT);
    cudaFuncSetAttribute(gemm_tc<MODE_POST>, cudaFuncAttributeMaxDynamicSharedMemorySize, SMEM_TOT);

    // 1) zero accumulators & degrees
    {
        int n4;
        n4 = (N1C * RC * DC) / 4;
        zero4_kernel<<<(n4 + 255) / 256, 256>>>((float4*)acc0, n4);
        n4 = N1C / 4;
        zero4_kernel<<<(n4 + 255) / 256, 256>>>((float4*)deg0, n4);
        n4 = (N2C * RC * DC) / 4;
        zero4_kernel<<<(n4 + 255) / 256, 256>>>((float4*)acc1, n4);
        n4 = N2C / 4;
        zero4_kernel<<<(n4 + 255) / 256, 256>>>((float4*)deg1, n4);
    }

    // 2) fold/split weights
    build_W_plain<<<(DC * DC + 255) / 256, 256>>>(preW, wpreh, wprel);
    build_W_plain<<<(DC * DC + 255) / 256, 256>>>(postW, wposth, wpostl);
    build_W_node<<<(KNODE * DC + 255) / 256, 256>>>(root0, basis0, comp0, w0h, w0l);
    build_W_node<<<(KNODE * DC + 255) / 256, 256>>>(root1, basis1, comp1, w1h, w1l);

    // 3) pre: h0 = relu(x @ preW + preB)
    gemm_tc<MODE_PRE><<<(N0C + 127) / 128, 256, SMEM_TOT>>>(
        x, nullptr, nullptr, wpreh, wprel, preB, nullptr, nullptr, h0, N0C, DC);

    // 4) edges layer 0
    edge_kernel<<<(E0C + 7) / 8, 256>>>(src0, dst0, eid0, etall, h0, acc0, deg0, E0C);

    // 5) node 0
    gemm_tc<MODE_NODE><<<(N1C + 127) / 128, 256, SMEM_TOT>>>(
        h0, acc0, deg0, w0h, w0l, bias0, g0, be0, h1, N1C, KNODE);

    // 6) edges layer 1
    edge_kernel<<<(E1C + 7) / 8, 256>>>(src1, dst1, eid1, etall, h1, acc1, deg1, E1C);

    // 7) node 1
    gemm_tc<MODE_NODE><<<(N2C + 127) / 128, 256, SMEM_TOT>>>(
        h1, acc1, deg1, w1h, w1l, bias1, g1, be1, h2, N2C, KNODE);

    // 8) post: out = h2 @ postW + postB
    gemm_tc<MODE_POST><<<(N2C + 127) / 128, 256, SMEM_TOT>>>(
        h2, nullptr, nullptr, wposth, wpostl, postB, nullptr, nullptr, (float*)d_out, N2C, DC);
}

// round 4
// speedup vs baseline: 1.2959x; 1.0271x over previous
#include <cuda_runtime.h>
#include <cuda_bf16.h>
#include <mma.h>
#include <cstdint>
#include <cstddef>

using namespace nvcuda;

// ---------------- problem constants ----------------
#define N0C 120000
#define N1C 30000
#define N2C 6000
#define E0C 480000
#define E1C 96000
#define DC  128
#define RC  8
#define NBC 4
#define KNODE (DC + RC*DC)   // 1152
#define CAP  128             // bucket capacity per dst
#define OVF_MAX 4096

// ---------------- device scratch ----------------
__device__ float g_h0[(size_t)N0C * DC];
__device__ float g_acc0[(size_t)N1C * RC * DC];
__device__ float g_h1[(size_t)N1C * DC];
__device__ float g_acc1[(size_t)N2C * RC * DC];
__device__ float g_h2[(size_t)N2C * DC];

__device__ int g_cnt0[N1C];
__device__ int g_cnt1[N2C];
__device__ unsigned int g_pay0[(size_t)N1C * CAP];
__device__ unsigned int g_pay1[(size_t)N2C * CAP];
__device__ int g_ovfn0[1];
__device__ int g_ovfn1[1];
__device__ uint2 g_ovf0[OVF_MAX];
__device__ uint2 g_ovf1[OVF_MAX];

// Folded, hi/lo-split weights W[k][n], bf16 row-major
__device__ __nv_bfloat16 g_WPre_hi[DC * DC];
__device__ __nv_bfloat16 g_WPre_lo[DC * DC];
__device__ __nv_bfloat16 g_W0_hi[KNODE * DC];
__device__ __nv_bfloat16 g_W0_lo[KNODE * DC];
__device__ __nv_bfloat16 g_W1_hi[KNODE * DC];
__device__ __nv_bfloat16 g_W1_lo[KNODE * DC];
__device__ __nv_bfloat16 g_WPost_hi[DC * DC];
__device__ __nv_bfloat16 g_WPost_lo[DC * DC];

// ---------------- zero counters ----------------
__global__ void zero_counters(int* c0, int* c1, int* o0, int* o1) {
    int i = blockIdx.x * blockDim.x + threadIdx.x;
    if (i < N1C) c0[i] = 0;
    if (i < N2C) c1[i] = 0;
    if (i == 0) { o0[0] = 0; o1[0] = 0; }
}

// ---------------- weight fold + split ----------------
__global__ void build_W_plain(const float* __restrict__ W,
                              __nv_bfloat16* __restrict__ hi,
                              __nv_bfloat16* __restrict__ lo) {
    int idx = blockIdx.x * blockDim.x + threadIdx.x;
    if (idx >= DC * DC) return;
    float v = W[idx];
    __nv_bfloat16 h = __float2bfloat16(v);
    hi[idx] = h;
    lo[idx] = __float2bfloat16(v - __bfloat162float(h));
}

__global__ void build_W_node(const float* __restrict__ root,
                             const float* __restrict__ basis,  // [NB,128,128]
                             const float* __restrict__ comp,   // [R,NB]
                             __nv_bfloat16* __restrict__ hi,
                             __nv_bfloat16* __restrict__ lo) {
    int idx = blockIdx.x * blockDim.x + threadIdx.x;
    if (idx >= KNODE * DC) return;
    int k = idx >> 7, n = idx & 127;
    float v;
    if (k < DC) {
        v = root[k * DC + n];
    } else {
        int r = (k - DC) >> 7;
        int i = (k - DC) & 127;
        v = 0.f;
        #pragma unroll
        for (int b = 0; b < NBC; b++)
            v += comp[r * NBC + b] * basis[((size_t)b * DC + i) * DC + n];
    }
    __nv_bfloat16 h = __float2bfloat16(v);
    hi[idx] = h;
    lo[idx] = __float2bfloat16(v - __bfloat162float(h));
}

// ---------------- edge bucketing (CSR-lite via fixed-capacity buckets) ----------------
__global__ void bucket_kernel(const int* __restrict__ src, const int* __restrict__ dst,
                              const int* __restrict__ eid, const int* __restrict__ et_all,
                              int* __restrict__ cnt, unsigned int* __restrict__ pay,
                              int* __restrict__ ovfn, uint2* __restrict__ ovf, int E) {
    int e = blockIdx.x * blockDim.x + threadIdx.x;
    if (e >= E) return;
    int d = dst[e];
    unsigned int p = (unsigned int)src[e] | ((unsigned int)et_all[eid[e]] << 24);
    int i = atomicAdd(&cnt[d], 1);
    if (i < CAP) {
        pay[(size_t)d * CAP + i] = p;
    } else {
        int o = atomicAdd(ovfn, 1);
        if (o < OVF_MAX) ovf[o] = make_uint2(p, (unsigned int)d);
    }
}

// ---------------- gather-aggregate: warp per dst ----------------
// acc[d, r, :] = (1/max(deg,1)) * sum_{edges e->d, etype r} h[src_e, :]
__global__ __launch_bounds__(256)
void gather_kernel(const int* __restrict__ cnt, const unsigned int* __restrict__ pay,
                   const float* __restrict__ h, float* __restrict__ acc, int N) {
    int d = blockIdx.x * 8 + (threadIdx.x >> 5);
    int lane = threadIdx.x & 31;
    if (d >= N) return;
    int ntot = cnt[d];
    int n = min(ntot, CAP);
    float a[RC][4];
    #pragma unroll
    for (int r = 0; r < RC; r++)
        #pragma unroll
        for (int q = 0; q < 4; q++) a[r][q] = 0.f;

    const unsigned int* pl = pay + (size_t)d * CAP;
    for (int j = 0; j < n; j++) {
        unsigned int p = __ldg(pl + j);
        int s = (int)(p & 0xFFFFFFu);
        int et = (int)(p >> 24);
        float4 v = *reinterpret_cast<const float4*>(h + (size_t)s * DC + lane * 4);
        #pragma unroll
        for (int r = 0; r < RC; r++) {
            if (et == r) {
                a[r][0] += v.x; a[r][1] += v.y; a[r][2] += v.z; a[r][3] += v.w;
            }
        }
    }
    float inv = 1.0f / fmaxf((float)ntot, 1.0f);
    float* out = acc + (size_t)d * (RC * DC) + lane * 4;
    #pragma unroll
    for (int r = 0; r < RC; r++) {
        float4 o = make_float4(a[r][0] * inv, a[r][1] * inv, a[r][2] * inv, a[r][3] * inv);
        *reinterpret_cast<float4*>(out + r * DC) = o;
    }
}

// ---------------- overflow fixup (normally 0 work) ----------------
__global__ void ovf_fix_kernel(const int* __restrict__ ovfn, const uint2* __restrict__ ovf,
                               const int* __restrict__ cnt,
                               const float* __restrict__ h, float* __restrict__ acc) {
    int n = min(ovfn[0], OVF_MAX);
    int w = threadIdx.x >> 5;
    int lane = threadIdx.x & 31;
    for (int k = w; k < n; k += 8) {
        uint2 pr = ovf[k];
        int s = (int)(pr.x & 0xFFFFFFu);
        int et = (int)(pr.x >> 24);
        int d = (int)pr.y;
        float inv = 1.0f / fmaxf((float)cnt[d], 1.0f);
        float4 v = *reinterpret_cast<const float4*>(h + (size_t)s * DC + lane * 4);
        float* a = acc + (size_t)d * (RC * DC) + et * DC + lane * 4;
        atomicAdd(a + 0, v.x * inv);
        atomicAdd(a + 1, v.y * inv);
        atomicAdd(a + 2, v.z * inv);
        atomicAdd(a + 3, v.w * inv);
    }
}

// ---------------- tensor-core fused GEMM (wmma bf16 split-precision) ----------------
enum { MODE_PRE = 0, MODE_NODE = 1, MODE_POST = 2 };

#define LDA 72      // A smem row stride (bf16 elements), 128 rows
#define LDB 136     // B smem row stride (bf16 elements), 64 rows
#define LDCS 132    // C smem row stride (floats), 128 rows

#define OFF_BIAS 0
#define OFF_G    512
#define OFF_BE   1024
#define OFF_DATA 2048
#define OFF_AHI  (OFF_DATA)
#define OFF_ALO  (OFF_AHI + 128*LDA*2)
#define OFF_BHI  (OFF_ALO + 128*LDA*2)
#define OFF_BLO  (OFF_BHI + 64*LDB*2)
#define SMEM_TOT (OFF_BLO + 64*LDB*2)   // 73728
#define OFF_C    (OFF_DATA)

template <int MODE>
__global__ __launch_bounds__(256)
void gemm_tc(const float* __restrict__ A,
             const float* __restrict__ ACC,
             const __nv_bfloat16* __restrict__ W_hi,
             const __nv_bfloat16* __restrict__ W_lo,
             const float* __restrict__ bias,
             const float* __restrict__ gamma,
             const float* __restrict__ beta,
             float* __restrict__ out,
             int M, int K) {
    extern __shared__ char smem[];
    const int t = threadIdx.x;
    const int w = t >> 5;
    const int wm = w >> 1;
    const int wn = w & 1;
    const int mBase = blockIdx.x * 128;

    float* s_bias = (float*)(smem + OFF_BIAS);
    float* s_g    = (float*)(smem + OFF_G);
    float* s_be   = (float*)(smem + OFF_BE);
    __nv_bfloat16* As_hi = (__nv_bfloat16*)(smem + OFF_AHI);
    __nv_bfloat16* As_lo = (__nv_bfloat16*)(smem + OFF_ALO);
    __nv_bfloat16* Bs_hi = (__nv_bfloat16*)(smem + OFF_BHI);
    __nv_bfloat16* Bs_lo = (__nv_bfloat16*)(smem + OFF_BLO);

    if (t < 128) {
        s_bias[t] = bias[t];
        if (MODE == MODE_NODE) {
            s_g[t]  = gamma[t];
            s_be[t] = beta[t];
        }
    }

    wmma::fragment<wmma::accumulator, 16, 16, 16, float> acc[2][4];
    #pragma unroll
    for (int i = 0; i < 2; i++)
        #pragma unroll
        for (int j = 0; j < 4; j++)
            wmma::fill_fragment(acc[i][j], 0.f);

    const int nCh = K >> 6;
    for (int c = 0; c < nCh; c++) {
        const int k0 = c * 64;
        __syncthreads();
        // ---- A stage: 128 rows x 64 k fp32 -> hi/lo bf16 ----
        #pragma unroll
        for (int it = 0; it < 8; it++) {
            int v = it * 256 + t;
            int row = v >> 4;
            int seg = v & 15;
            int kk = k0 + seg * 4;
            int g = mBase + row;
            float4 av = make_float4(0.f, 0.f, 0.f, 0.f);
            if (g < M) {
                if (MODE != MODE_NODE || kk < DC) {
                    av = *reinterpret_cast<const float4*>(A + (size_t)g * DC + kk);
                } else {
                    av = *reinterpret_cast<const float4*>(ACC + (size_t)g * (RC * DC) + (kk - DC));
                }
            }
            __nv_bfloat162 h01 = __floats2bfloat162_rn(av.x, av.y);
            __nv_bfloat162 h23 = __floats2bfloat162_rn(av.z, av.w);
            float rx = av.x - __bfloat162float(__low2bfloat16(h01));
            float ry = av.y - __bfloat162float(__high2bfloat16(h01));
            float rz = av.z - __bfloat162float(__low2bfloat16(h23));
            float rw = av.w - __bfloat162float(__high2bfloat16(h23));
            __nv_bfloat162 l01 = __floats2bfloat162_rn(rx, ry);
            __nv_bfloat162 l23 = __floats2bfloat162_rn(rz, rw);
            uint2 hp, lp;
            hp.x = *(uint32_t*)&h01; hp.y = *(uint32_t*)&h23;
            lp.x = *(uint32_t*)&l01; lp.y = *(uint32_t*)&l23;
            int off = row * LDA + seg * 4;
            *reinterpret_cast<uint2*>(As_hi + off) = hp;
            *reinterpret_cast<uint2*>(As_lo + off) = lp;
        }
        // ---- B stage ----
        #pragma unroll
        for (int it = 0; it < 4; it++) {
            int v = it * 256 + t;
            int row = v >> 4;
            int col8 = (v & 15) * 8;
            const float4* srcH = reinterpret_cast<const float4*>(W_hi + (size_t)(k0 + row) * DC + col8);
            const float4* srcL = reinterpret_cast<const float4*>(W_lo + (size_t)(k0 + row) * DC + col8);
            *reinterpret_cast<float4*>(Bs_hi + row * LDB + col8) = *srcH;
            *reinterpret_cast<float4*>(Bs_lo + row * LDB + col8) = *srcL;
        }
        __syncthreads();
        // ---- compute ----
        #pragma unroll
        for (int ks = 0; ks < 4; ks++) {
            wmma::fragment<wmma::matrix_a, 16, 16, 16, __nv_bfloat16, wmma::row_major> a_hi[2], a_lo[2];
            #pragma unroll
            for (int i = 0; i < 2; i++) {
                wmma::load_matrix_sync(a_hi[i], As_hi + (wm * 32 + i * 16) * LDA + ks * 16, LDA);
                wmma::load_matrix_sync(a_lo[i], As_lo + (wm * 32 + i * 16) * LDA + ks * 16, LDA);
            }
            #pragma unroll
            for (int j = 0; j < 4; j++) {
                wmma::fragment<wmma::matrix_b, 16, 16, 16, __nv_bfloat16, wmma::row_major> b_hi, b_lo;
                wmma::load_matrix_sync(b_hi, Bs_hi + (ks * 16) * LDB + wn * 64 + j * 16, LDB);
                wmma::load_matrix_sync(b_lo, Bs_lo + (ks * 16) * LDB + wn * 64 + j * 16, LDB);
                #pragma unroll
                for (int i = 0; i < 2; i++) {
                    wmma::mma_sync(acc[i][j], a_hi[i], b_hi, acc[i][j]);
                    wmma::mma_sync(acc[i][j], a_hi[i], b_lo, acc[i][j]);
                    wmma::mma_sync(acc[i][j], a_lo[i], b_hi, acc[i][j]);
                }
            }
        }
    }

    __syncthreads();
    float* Cs = (float*)(smem + OFF_C);
    #pragma unroll
    for (int i = 0; i < 2; i++)
        #pragma unroll
        for (int j = 0; j < 4; j++)
            wmma::store_matrix_sync(Cs + (wm * 32 + i * 16) * LDCS + wn * 64 + j * 16,
                                    acc[i][j], LDCS, wmma::mem_row_major);
    __syncthreads();

    {
        int row = t >> 1;
        int half = t & 1;
        int grow = mBase + row;
        const float* crow = Cs + row * LDCS + half * 64;
        float v[64];
        #pragma unroll
        for (int q = 0; q < 16; q++) {
            float4 cv = *reinterpret_cast<const float4*>(crow + q * 4);
            v[q * 4 + 0] = cv.x + s_bias[half * 64 + q * 4 + 0];
            v[q * 4 + 1] = cv.y + s_bias[half * 64 + q * 4 + 1];
            v[q * 4 + 2] = cv.z + s_bias[half * 64 + q * 4 + 2];
            v[q * 4 + 3] = cv.w + s_bias[half * 64 + q * 4 + 3];
        }
        if (MODE == MODE_NODE) {
            float s1 = 0.f, s2 = 0.f;
            #pragma unroll
            for (int j = 0; j < 64; j++) { s1 += v[j]; s2 += v[j] * v[j]; }
            s1 += __shfl_xor_sync(0xffffffffu, s1, 1);
            s2 += __shfl_xor_sync(0xffffffffu, s2, 1);
            float mu = s1 * (1.f / 128.f);
            float var = s2 * (1.f / 128.f) - mu * mu;
            float rs = rsqrtf(var + 1e-5f);
            #pragma unroll
            for (int j = 0; j < 64; j++)
                v[j] = fmaxf((v[j] - mu) * rs * s_g[half * 64 + j] + s_be[half * 64 + j], 0.f);
        } else if (MODE == MODE_PRE) {
            #pragma unroll
            for (int j = 0; j < 64; j++) v[j] = fmaxf(v[j], 0.f);
        }
        if (grow < M) {
            #pragma unroll
            for (int q = 0; q < 16; q++) {
                float4 o = make_float4(v[q * 4], v[q * 4 + 1], v[q * 4 + 2], v[q * 4 + 3]);
                *reinterpret_cast<float4*>(out + (size_t)grow * DC + half * 64 + q * 4) = o;
            }
        }
    }
}

// ---------------- launch ----------------
extern "C" void kernel_launch(void* const* d_in, const int* in_sizes, int n_in,
                              void* d_out, int out_size) {
    const float* x     = (const float*)d_in[0];
    const int*   src0  = (const int*)d_in[1];
    const int*   dst0  = (const int*)d_in[2];
    const int*   eid0  = (const int*)d_in[3];
    const int*   src1  = (const int*)d_in[4];
    const int*   dst1  = (const int*)d_in[5];
    const int*   eid1  = (const int*)d_in[6];
    const int*   etall = (const int*)d_in[7];
    const float* preW  = (const float*)d_in[8];
    const float* preB  = (const float*)d_in[9];
    const float* basis0= (const float*)d_in[10];
    const float* comp0 = (const float*)d_in[11];
    const float* root0 = (const float*)d_in[12];
    const float* bias0 = (const float*)d_in[13];
    const float* g0    = (const float*)d_in[14];
    const float* be0   = (const float*)d_in[15];
    const float* basis1= (const float*)d_in[16];
    const float* comp1 = (const float*)d_in[17];
    const float* root1 = (const float*)d_in[18];
    const float* bias1 = (const float*)d_in[19];
    const float* g1    = (const float*)d_in[20];
    const float* be1   = (const float*)d_in[21];
    const float* postW = (const float*)d_in[22];
    const float* postB = (const float*)d_in[23];

    float *h0, *acc0, *h1, *acc1, *h2;
    int *cnt0, *cnt1, *ovfn0, *ovfn1;
    unsigned int *pay0, *pay1;
    uint2 *ovf0, *ovf1;
    __nv_bfloat16 *wpreh, *wprel, *w0h, *w0l, *w1h, *w1l, *wposth, *wpostl;
    cudaGetSymbolAddress((void**)&h0,   g_h0);
    cudaGetSymbolAddress((void**)&acc0, g_acc0);
    cudaGetSymbolAddress((void**)&h1,   g_h1);
    cudaGetSymbolAddress((void**)&acc1, g_acc1);
    cudaGetSymbolAddress((void**)&h2,   g_h2);
    cudaGetSymbolAddress((void**)&cnt0, g_cnt0);
    cudaGetSymbolAddress((void**)&cnt1, g_cnt1);
    cudaGetSymbolAddress((void**)&pay0, g_pay0);
    cudaGetSymbolAddress((void**)&pay1, g_pay1);
    cudaGetSymbolAddress((void**)&ovfn0, g_ovfn0);
    cudaGetSymbolAddress((void**)&ovfn1, g_ovfn1);
    cudaGetSymbolAddress((void**)&ovf0, g_ovf0);
    cudaGetSymbolAddress((void**)&ovf1, g_ovf1);
    cudaGetSymbolAddress((void**)&wpreh, g_WPre_hi);
    cudaGetSymbolAddress((void**)&wprel, g_WPre_lo);
    cudaGetSymbolAddress((void**)&w0h,   g_W0_hi);
    cudaGetSymbolAddress((void**)&w0l,   g_W0_lo);
    cudaGetSymbolAddress((void**)&w1h,   g_W1_hi);
    cudaGetSymbolAddress((void**)&w1l,   g_W1_lo);
    cudaGetSymbolAddress((void**)&wposth, g_WPost_hi);
    cudaGetSymbolAddress((void**)&wpostl, g_WPost_lo);

    cudaFuncSetAttribute(gemm_tc<MODE_PRE>,  cudaFuncAttributeMaxDynamicSharedMemorySize, SMEM_TOT);
    cudaFuncSetAttribute(gemm_tc<MODE_NODE>, cudaFuncAttributeMaxDynamicSharedMemorySize, SMEM_TOT);
    cudaFuncSetAttribute(gemm_tc<MODE_POST>, cudaFuncAttributeMaxDynamicSharedMemorySize, SMEM_TOT);

    // 1) zero counters + bucket both edge sets (index-only work)
    zero_counters<<<(N1C + 255) / 256, 256>>>(cnt0, cnt1, ovfn0, ovfn1);
    bucket_kernel<<<(E0C + 255) / 256, 256>>>(src0, dst0, eid0, etall, cnt0, pay0, ovfn0, ovf0, E0C);
    bucket_kernel<<<(E1C + 255) / 256, 256>>>(src1, dst1, eid1, etall, cnt1, pay1, ovfn1, ovf1, E1C);

    // 2) fold/split weights
    build_W_plain<<<(DC * DC + 255) / 256, 256>>>(preW, wpreh, wprel);
    build_W_plain<<<(DC * DC + 255) / 256, 256>>>(postW, wposth, wpostl);
    build_W_node<<<(KNODE * DC + 255) / 256, 256>>>(root0, basis0, comp0, w0h, w0l);
    build_W_node<<<(KNODE * DC + 255) / 256, 256>>>(root1, basis1, comp1, w1h, w1l);

    // 3) pre: h0 = relu(x @ preW + preB)
    gemm_tc<MODE_PRE><<<(N0C + 127) / 128, 256, SMEM_TOT>>>(
        x, nullptr, wpreh, wprel, preB, nullptr, nullptr, h0, N0C, DC);

    // 4) gather layer 0 (acc0 = per-relation mean-ready sums / deg)
    gather_kernel<<<(N1C + 7) / 8, 256>>>(cnt0, pay0, h0, acc0, N1C);
    ovf_fix_kernel<<<1, 256>>>(ovfn0, ovf0, cnt0, h0, acc0);

    // 5) node 0
    gemm_tc<MODE_NODE><<<(N1C + 127) / 128, 256, SMEM_TOT>>>(
        h0, acc0, w0h, w0l, bias0, g0, be0, h1, N1C, KNODE);

    // 6) gather layer 1
    gather_kernel<<<(N2C + 7) / 8, 256>>>(cnt1, pay1, h1, acc1, N2C);
    ovf_fix_kernel<<<1, 256>>>(ovfn1, ovf1, cnt1, h1, acc1);

    // 7) node 1
    gemm_tc<MODE_NODE><<<(N2C + 127) / 128, 256, SMEM_TOT>>>(
        h1, acc1, w1h, w1l, bias1, g1, be1, h2, N2C, KNODE);

    // 8) post: out = h2 @ postW + postB
    gemm_tc<MODE_POST><<<(N2C + 127) / 128, 256, SMEM_TOT>>>(
        h2, nullptr, wposth, wpostl, postB, nullptr, nullptr, (float*)d_out, N2C, DC);
}

// round 5
// speedup vs baseline: 2.9441x; 2.2719x over previous
#include <cuda_runtime.h>
#include <cuda_fp16.h>
#include <mma.h>
#include <cstdint>
#include <cstddef>

using namespace nvcuda;

// ---------------- problem constants ----------------
#define N0C 120000
#define N1C 30000
#define N2C 6000
#define E0C 480000
#define E1C 96000
#define DC  128
#define RC  8
#define NBC 4
#define KNODE (DC + RC*DC)   // 1152
#define CAP  128
#define OVF_MAX 4096

// ---------------- device scratch ----------------
__device__ __half g_xh[(size_t)N0C * DC];
__device__ __half g_h0h[(size_t)N0C * DC];
__device__ __half g_acc0h[(size_t)N1C * RC * DC];
__device__ __half g_h1h[(size_t)N1C * DC];
__device__ __half g_acc1h[(size_t)N2C * RC * DC];
__device__ __half g_h2h[(size_t)N2C * DC];

__device__ int g_cnt0[N1C];
__device__ int g_cnt1[N2C];
__device__ unsigned int g_pay0[(size_t)N1C * CAP];
__device__ unsigned int g_pay1[(size_t)N2C * CAP];
__device__ int g_ovfn0[1];
__device__ int g_ovfn1[1];
__device__ uint2 g_ovf0[OVF_MAX];
__device__ uint2 g_ovf1[OVF_MAX];

// Folded weights W[k][n], fp16 hi/lo split, row-major
__device__ __half g_WPre_hi[DC * DC];
__device__ __half g_WPre_lo[DC * DC];
__device__ __half g_W0_hi[KNODE * DC];
__device__ __half g_W0_lo[KNODE * DC];
__device__ __half g_W1_hi[KNODE * DC];
__device__ __half g_W1_lo[KNODE * DC];
__device__ __half g_WPost_hi[DC * DC];
__device__ __half g_WPost_lo[DC * DC];

// ---------------- helpers ----------------
__device__ __forceinline__ uint32_t smem_u32(const void* p) {
    uint32_t a;
    asm("{ .reg .u64 t; cvta.to.shared.u64 t, %1; cvt.u32.u64 %0, t; }" : "=r"(a) : "l"(p));
    return a;
}
__device__ __forceinline__ void cp16(uint32_t dst, const void* src, int sz) {
    asm volatile("cp.async.cg.shared.global [%0], [%1], 16, %2;"
                 :: "r"(dst), "l"(src), "r"(sz) : "memory");
}
__device__ __forceinline__ void cp_commit() {
    asm volatile("cp.async.commit_group;" ::: "memory");
}
template <int N>
__device__ __forceinline__ void cp_wait() {
    asm volatile("cp.async.wait_group %0;" :: "n"(N) : "memory");
}

// ---------------- small kernels ----------------
__global__ void zero_counters(int* c0, int* c1, int* o0, int* o1) {
    int i = blockIdx.x * blockDim.x + threadIdx.x;
    if (i < N1C) c0[i] = 0;
    if (i < N2C) c1[i] = 0;
    if (i == 0) { o0[0] = 0; o1[0] = 0; }
}

__global__ void f32_to_f16(const float4* __restrict__ in, uint2* __restrict__ out, int n4) {
    int i = blockIdx.x * blockDim.x + threadIdx.x;
    if (i >= n4) return;
    float4 v = in[i];
    __half2 a = __floats2half2_rn(v.x, v.y);
    __half2 b = __floats2half2_rn(v.z, v.w);
    uint2 o;
    o.x = *(uint32_t*)&a; o.y = *(uint32_t*)&b;
    out[i] = o;
}

__global__ void build_W_plain(const float* __restrict__ W,
                              __half* __restrict__ hi, __half* __restrict__ lo) {
    int idx = blockIdx.x * blockDim.x + threadIdx.x;
    if (idx >= DC * DC) return;
    float v = W[idx];
    __half h = __float2half(v);
    hi[idx] = h;
    lo[idx] = __float2half(v - __half2float(h));
}

__global__ void build_W_node(const float* __restrict__ root,
                             const float* __restrict__ basis,
                             const float* __restrict__ comp,
                             __half* __restrict__ hi, __half* __restrict__ lo) {
    int idx = blockIdx.x * blockDim.x + threadIdx.x;
    if (idx >= KNODE * DC) return;
    int k = idx >> 7, n = idx & 127;
    float v;
    if (k < DC) {
        v = root[k * DC + n];
    } else {
        int r = (k - DC) >> 7;
        int i = (k - DC) & 127;
        v = 0.f;
        #pragma unroll
        for (int b = 0; b < NBC; b++)
            v += comp[r * NBC + b] * basis[((size_t)b * DC + i) * DC + n];
    }
    __half h = __float2half(v);
    hi[idx] = h;
    lo[idx] = __float2half(v - __half2float(h));
}

// ---------------- edge bucketing ----------------
__global__ void bucket_kernel(const int* __restrict__ src, const int* __restrict__ dst,
                              const int* __restrict__ eid, const int* __restrict__ et_all,
                              int* __restrict__ cnt, unsigned int* __restrict__ pay,
                              int* __restrict__ ovfn, uint2* __restrict__ ovf, int E) {
    int e = blockIdx.x * blockDim.x + threadIdx.x;
    if (e >= E) return;
    int d = dst[e];
    unsigned int p = (unsigned int)src[e] | ((unsigned int)et_all[eid[e]] << 24);
    int i = atomicAdd(&cnt[d], 1);
    if (i < CAP) {
        pay[(size_t)d * CAP + i] = p;
    } else {
        int o = atomicAdd(ovfn, 1);
        if (o < OVF_MAX) ovf[o] = make_uint2(p, (unsigned int)d);
    }
}

// ---------------- gather-aggregate: warp per dst, fp16 in/out ----------------
__global__ __launch_bounds__(256)
void gather_kernel(const int* __restrict__ cnt, const unsigned int* __restrict__ pay,
                   const __half* __restrict__ h, __half* __restrict__ acc, int N) {
    int d = blockIdx.x * 8 + (threadIdx.x >> 5);
    int lane = threadIdx.x & 31;
    if (d >= N) return;
    int ntot = cnt[d];
    int n = min(ntot, CAP);
    float a[RC][4];
    #pragma unroll
    for (int r = 0; r < RC; r++)
        #pragma unroll
        for (int q = 0; q < 4; q++) a[r][q] = 0.f;

    const unsigned int* pl = pay + (size_t)d * CAP;
    for (int j = 0; j < n; j++) {
        unsigned int p = __ldg(pl + j);
        int s = (int)(p & 0xFFFFFFu);
        int et = (int)(p >> 24);
        uint2 u = *reinterpret_cast<const uint2*>(h + (size_t)s * DC + lane * 4);
        __half2 p0 = *(__half2*)&u.x;
        __half2 p1 = *(__half2*)&u.y;
        float2 f0 = __half22float2(p0);
        float2 f1 = __half22float2(p1);
        #pragma unroll
        for (int r = 0; r < RC; r++) {
            if (et == r) {
                a[r][0] += f0.x; a[r][1] += f0.y; a[r][2] += f1.x; a[r][3] += f1.y;
            }
        }
    }
    float inv = 1.0f / fmaxf((float)ntot, 1.0f);
    __half* out = acc + (size_t)d * (RC * DC) + lane * 4;
    #pragma unroll
    for (int r = 0; r < RC; r++) {
        __half2 o0 = __floats2half2_rn(a[r][0] * inv, a[r][1] * inv);
        __half2 o1 = __floats2half2_rn(a[r][2] * inv, a[r][3] * inv);
        uint2 o;
        o.x = *(uint32_t*)&o0; o.y = *(uint32_t*)&o1;
        *reinterpret_cast<uint2*>(out + r * DC) = o;
    }
}

// ---------------- overflow fixup (normally 0 work) ----------------
__global__ void ovf_fix_kernel(const int* __restrict__ ovfn, const uint2* __restrict__ ovf,
                               const int* __restrict__ cnt,
                               const __half* __restrict__ h, __half* __restrict__ acc) {
    int n = min(ovfn[0], OVF_MAX);
    int w = threadIdx.x >> 5;
    int lane = threadIdx.x & 31;
    for (int k = w; k < n; k += 8) {
        uint2 pr = ovf[k];
        int s = (int)(pr.x & 0xFFFFFFu);
        int et = (int)(pr.x >> 24);
        int d = (int)pr.y;
        float inv = 1.0f / fmaxf((float)cnt[d], 1.0f);
        __half2 iv = __float2half2_rn(inv);
        uint2 u = *reinterpret_cast<const uint2*>(h + (size_t)s * DC + lane * 4);
        __half2 p0 = __hmul2(*(__half2*)&u.x, iv);
        __half2 p1 = __hmul2(*(__half2*)&u.y, iv);
        __half2* a = (__half2*)(acc + (size_t)d * (RC * DC) + et * DC + lane * 4);
        atomicAdd(a + 0, p0);
        atomicAdd(a + 1, p1);
    }
}

// ---------------- GEMM: fp16 A, split-fp16 B, cp.async double-buffered ----------------
enum { MODE_PRE = 0, MODE_NODE = 1, MODE_POST = 2 };

#define LDA 72
#define LDB 136
#define LDCS 132

#define A_BUF 18432            // 128*72*2
#define B_BUF 34816            // 2 * 64*136*2
#define OFF_BIAS 0
#define OFF_G    512
#define OFF_BE   1024
#define OFF_A    2048
#define OFF_B    (OFF_A + 2*A_BUF)       // 38912
#define SMEM_TOT (OFF_B + 2*B_BUF)       // 108544
#define OFF_C    OFF_A                   // 128*132*4 = 67584 fits

template <int MODE>
__global__ __launch_bounds__(256, 2)
void gemm_tc(const __half* __restrict__ A,
             const __half* __restrict__ ACC,
             const __half* __restrict__ Whi,
             const __half* __restrict__ Wlo,
             const float* __restrict__ bias,
             const float* __restrict__ gamma,
             const float* __restrict__ beta,
             __half* __restrict__ outH,
             float* __restrict__ outF,
             int M, int K) {
    extern __shared__ char smem[];
    const uint32_t sb = smem_u32(smem);
    const int t = threadIdx.x;
    const int w = t >> 5;
    const int wm = w >> 1;
    const int wn = w & 1;
    const int mBase = blockIdx.x * 128;

    float* s_bias = (float*)(smem + OFF_BIAS);
    float* s_g    = (float*)(smem + OFF_G);
    float* s_be   = (float*)(smem + OFF_BE);

    if (t < 128) {
        s_bias[t] = bias[t];
        if (MODE == MODE_NODE) { s_g[t] = gamma[t]; s_be[t] = beta[t]; }
    }

    wmma::fragment<wmma::accumulator, 16, 16, 16, float> acc[2][4];
    #pragma unroll
    for (int i = 0; i < 2; i++)
        #pragma unroll
        for (int j = 0; j < 4; j++)
            wmma::fill_fragment(acc[i][j], 0.f);

    const int nCh = K >> 6;

    // staging issue for chunk c into buffer c&1
    auto issue = [&](int c) {
        int buf = c & 1;
        int k0 = c * 64;
        #pragma unroll
        for (int it = 0; it < 4; it++) {
            int v = it * 256 + t;
            int row = v >> 3, seg = v & 7;
            int g = mBase + row;
            bool ok = g < M;
            const __half* src;
            if (MODE == MODE_NODE && k0 >= DC)
                src = ACC + (size_t)(ok ? g : 0) * (RC * DC) + (k0 - DC) + seg * 8;
            else
                src = A + (size_t)(ok ? g : 0) * DC + k0 + seg * 8;
            cp16(sb + OFF_A + buf * A_BUF + row * (LDA * 2) + seg * 16, src, ok ? 16 : 0);
        }
        #pragma unroll
        for (int it = 0; it < 4; it++) {
            int v = it * 256 + t;
            int row = v >> 4, seg = v & 15;
            const __half* sh = Whi + (size_t)(k0 + row) * DC + seg * 8;
            const __half* sl = Wlo + (size_t)(k0 + row) * DC + seg * 8;
            uint32_t d0 = sb + OFF_B + buf * B_BUF + row * (LDB * 2) + seg * 16;
            cp16(d0, sh, 16);
            cp16(d0 + 64 * (LDB * 2), sl, 16);
        }
    };

    issue(0);
    cp_commit();

    for (int c = 0; c < nCh; c++) {
        if (c + 1 < nCh) {
            issue(c + 1);
            cp_commit();
            cp_wait<1>();
        } else {
            cp_wait<0>();
        }
        __syncthreads();

        int buf = c & 1;
        const __half* As = (const __half*)(smem + OFF_A + buf * A_BUF);
        const __half* Bh = (const __half*)(smem + OFF_B + buf * B_BUF);
        const __half* Bl = Bh + 64 * LDB;

        #pragma unroll
        for (int ks = 0; ks < 4; ks++) {
            wmma::fragment<wmma::matrix_a, 16, 16, 16, __half, wmma::row_major> a[2];
            #pragma unroll
            for (int i = 0; i < 2; i++)
                wmma::load_matrix_sync(a[i], As + (wm * 32 + i * 16) * LDA + ks * 16, LDA);
            #pragma unroll
            for (int j = 0; j < 4; j++) {
                wmma::fragment<wmma::matrix_b, 16, 16, 16, __half, wmma::row_major> bh, bl;
                wmma::load_matrix_sync(bh, Bh + (ks * 16) * LDB + wn * 64 + j * 16, LDB);
                wmma::load_matrix_sync(bl, Bl + (ks * 16) * LDB + wn * 64 + j * 16, LDB);
                #pragma unroll
                for (int i = 0; i < 2; i++) {
                    wmma::mma_sync(acc[i][j], a[i], bh, acc[i][j]);
                    wmma::mma_sync(acc[i][j], a[i], bl, acc[i][j]);
                }
            }
        }
        __syncthreads();
    }

    // ---- write C to smem ----
    float* Cs = (float*)(smem + OFF_C);
    #pragma unroll
    for (int i = 0; i < 2; i++)
        #pragma unroll
        for (int j = 0; j < 4; j++)
            wmma::store_matrix_sync(Cs + (wm * 32 + i * 16) * LDCS + wn * 64 + j * 16,
                                    acc[i][j], LDCS, wmma::mem_row_major);
    __syncthreads();

    // ---- epilogue: 2 threads per row ----
    {
        int row = t >> 1;
        int half = t & 1;
        int grow = mBase + row;
        const float* crow = Cs + row * LDCS + half * 64;
        float v[64];
        #pragma unroll
        for (int q = 0; q < 16; q++) {
            float4 cv = *reinterpret_cast<const float4*>(crow + q * 4);
            v[q * 4 + 0] = cv.x + s_bias[half * 64 + q * 4 + 0];
            v[q * 4 + 1] = cv.y + s_bias[half * 64 + q * 4 + 1];
            v[q * 4 + 2] = cv.z + s_bias[half * 64 + q * 4 + 2];
            v[q * 4 + 3] = cv.w + s_bias[half * 64 + q * 4 + 3];
        }
        if (MODE == MODE_NODE) {
            float s1 = 0.f, s2 = 0.f;
            #pragma unroll
            for (int j = 0; j < 64; j++) { s1 += v[j]; s2 += v[j] * v[j]; }
            s1 += __shfl_xor_sync(0xffffffffu, s1, 1);
            s2 += __shfl_xor_sync(0xffffffffu, s2, 1);
            float mu = s1 * (1.f / 128.f);
            float var = s2 * (1.f / 128.f) - mu * mu;
            float rs = rsqrtf(var + 1e-5f);
            #pragma unroll
            for (int j = 0; j < 64; j++)
                v[j] = fmaxf((v[j] - mu) * rs * s_g[half * 64 + j] + s_be[half * 64 + j], 0.f);
        } else if (MODE == MODE_PRE) {
            #pragma unroll
            for (int j = 0; j < 64; j++) v[j] = fmaxf(v[j], 0.f);
        }
        if (grow < M) {
            if (MODE == MODE_POST) {
                #pragma unroll
                for (int q = 0; q < 16; q++) {
                    float4 o = make_float4(v[q * 4], v[q * 4 + 1], v[q * 4 + 2], v[q * 4 + 3]);
                    *reinterpret_cast<float4*>(outF + (size_t)grow * DC + half * 64 + q * 4) = o;
                }
            } else {
                #pragma unroll
                for (int q = 0; q < 8; q++) {
                    __half2 h0 = __floats2half2_rn(v[q * 8 + 0], v[q * 8 + 1]);
                    __half2 h1 = __floats2half2_rn(v[q * 8 + 2], v[q * 8 + 3]);
                    __half2 h2 = __floats2half2_rn(v[q * 8 + 4], v[q * 8 + 5]);
                    __half2 h3 = __floats2half2_rn(v[q * 8 + 6], v[q * 8 + 7]);
                    uint4 o;
                    o.x = *(uint32_t*)&h0; o.y = *(uint32_t*)&h1;
                    o.z = *(uint32_t*)&h2; o.w = *(uint32_t*)&h3;
                    *reinterpret_cast<uint4*>(outH + (size_t)grow * DC + half * 64 + q * 8) = o;
                }
            }
        }
    }
}

// ---------------- launch ----------------
extern "C" void kernel_launch(void* const* d_in, const int* in_sizes, int n_in,
                              void* d_out, int out_size) {
    const float* x     = (const float*)d_in[0];
    const int*   src0  = (const int*)d_in[1];
    const int*   dst0  = (const int*)d_in[2];
    const int*   eid0  = (const int*)d_in[3];
    const int*   src1  = (const int*)d_in[4];
    const int*   dst1  = (const int*)d_in[5];
    const int*   eid1  = (const int*)d_in[6];
    const int*   etall = (const int*)d_in[7];
    const float* preW  = (const float*)d_in[8];
    const float* preB  = (const float*)d_in[9];
    const float* basis0= (const float*)d_in[10];
    const float* comp0 = (const float*)d_in[11];
    const float* root0 = (const float*)d_in[12];
    const float* bias0 = (const float*)d_in[13];
    const float* g0    = (const float*)d_in[14];
    const float* be0   = (const float*)d_in[15];
    const float* basis1= (const float*)d_in[16];
    const float* comp1 = (const float*)d_in[17];
    const float* root1 = (const float*)d_in[18];
    const float* bias1 = (const float*)d_in[19];
    const float* g1    = (const float*)d_in[20];
    const float* be1   = (const float*)d_in[21];
    const float* postW = (const float*)d_in[22];
    const float* postB = (const float*)d_in[23];

    __half *xh, *h0h, *acc0h, *h1h, *acc1h, *h2h;
    int *cnt0, *cnt1, *ovfn0, *ovfn1;
    unsigned int *pay0, *pay1;
    uint2 *ovf0, *ovf1;
    __half *wpreh, *wprel, *w0h, *w0l, *w1h, *w1l, *wposth, *wpostl;
    cudaGetSymbolAddress((void**)&xh,    g_xh);
    cudaGetSymbolAddress((void**)&h0h,   g_h0h);
    cudaGetSymbolAddress((void**)&acc0h, g_acc0h);
    cudaGetSymbolAddress((void**)&h1h,   g_h1h);
    cudaGetSymbolAddress((void**)&acc1h, g_acc1h);
    cudaGetSymbolAddress((void**)&h2h,   g_h2h);
    cudaGetSymbolAddress((void**)&cnt0,  g_cnt0);
    cudaGetSymbolAddress((void**)&cnt1,  g_cnt1);
    cudaGetSymbolAddress((void**)&pay0,  g_pay0);
    cudaGetSymbolAddress((void**)&pay1,  g_pay1);
    cudaGetSymbolAddress((void**)&ovfn0, g_ovfn0);
    cudaGetSymbolAddress((void**)&ovfn1, g_ovfn1);
    cudaGetSymbolAddress((void**)&ovf0,  g_ovf0);
    cudaGetSymbolAddress((void**)&ovf1,  g_ovf1);
    cudaGetSymbolAddress((void**)&wpreh, g_WPre_hi);
    cudaGetSymbolAddress((void**)&wprel, g_WPre_lo);
    cudaGetSymbolAddress((void**)&w0h,   g_W0_hi);
    cudaGetSymbolAddress((void**)&w0l,   g_W0_lo);
    cudaGetSymbolAddress((void**)&w1h,   g_W1_hi);
    cudaGetSymbolAddress((void**)&w1l,   g_W1_lo);
    cudaGetSymbolAddress((void**)&wposth, g_WPost_hi);
    cudaGetSymbolAddress((void**)&wpostl, g_WPost_lo);

    cudaFuncSetAttribute(gemm_tc<MODE_PRE>,  cudaFuncAttributeMaxDynamicSharedMemorySize, SMEM_TOT);
    cudaFuncSetAttribute(gemm_tc<MODE_NODE>, cudaFuncAttributeMaxDynamicSharedMemorySize, SMEM_TOT);
    cudaFuncSetAttribute(gemm_tc<MODE_POST>, cudaFuncAttributeMaxDynamicSharedMemorySize, SMEM_TOT);

    // 1-3: counters + bucketing
    zero_counters<<<(N1C + 255) / 256, 256>>>(cnt0, cnt1, ovfn0, ovfn1);
    bucket_kernel<<<(E0C + 255) / 256, 256>>>(src0, dst0, eid0, etall, cnt0, pay0, ovfn0, ovf0, E0C);
    bucket_kernel<<<(E1C + 255) / 256, 256>>>(src1, dst1, eid1, etall, cnt1, pay1, ovfn1, ovf1, E1C);

    // 4-5: pre-weights + x conversion (keeps pre-GEMM at launch #6 for ncu)
    build_W_plain<<<(DC * DC + 255) / 256, 256>>>(preW, wpreh, wprel);
    {
        int n4 = N0C * DC / 4;
        f32_to_f16<<<(n4 + 255) / 256, 256>>>((const float4*)x, (uint2*)xh, n4);
    }

    // 6: pre-GEMM  h0h = relu(x @ preW + preB)
    gemm_tc<MODE_PRE><<<(N0C + 127) / 128, 256, SMEM_TOT>>>(
        xh, nullptr, wpreh, wprel, preB, nullptr, nullptr, h0h, nullptr, N0C, DC);

    // 7: node0 weights
    build_W_node<<<(KNODE * DC + 255) / 256, 256>>>(root0, basis0, comp0, w0h, w0l);

    // 8-9: gather layer 0 + overflow fixup
    gather_kernel<<<(N1C + 7) / 8, 256>>>(cnt0, pay0, h0h, acc0h, N1C);
    ovf_fix_kernel<<<1, 256>>>(ovfn0, ovf0, cnt0, h0h, acc0h);

    // 10: node0 GEMM
    gemm_tc<MODE_NODE><<<(N1C + 127) / 128, 256, SMEM_TOT>>>(
        h0h, acc0h, w0h, w0l, bias0, g0, be0, h1h, nullptr, N1C, KNODE);

    // 11: node1 weights
    build_W_node<<<(KNODE * DC + 255) / 256, 256>>>(root1, basis1, comp1, w1h, w1l);

    // 12-13: gather layer 1 + fixup
    gather_kernel<<<(N2C + 7) / 8, 256>>>(cnt1, pay1, h1h, acc1h, N2C);
    ovf_fix_kernel<<<1, 256>>>(ovfn1, ovf1, cnt1, h1h, acc1h);

    // 14: node1 GEMM
    gemm_tc<MODE_NODE><<<(N2C + 127) / 128, 256, SMEM_TOT>>>(
        h1h, acc1h, w1h, w1l, bias1, g1, be1, h2h, nullptr, N2C, KNODE);

    // 15: post weights
    build_W_plain<<<(DC * DC + 255) / 256, 256>>>(postW, wposth, wpostl);

    // 16: post GEMM -> fp32 out
    gemm_tc<MODE_POST><<<(N2C + 127) / 128, 256, SMEM_TOT>>>(
        h2h, nullptr, wposth, wpostl, postB, nullptr, nullptr, nullptr, (float*)d_out, N2C, DC);
}

// round 7
// speedup vs baseline: 3.1732x; 1.0778x over previous
#include <cuda_runtime.h>
#include <cuda_fp16.h>
#include <mma.h>
#include <cstdint>
#include <cstddef>

using namespace nvcuda;

// ---------------- problem constants ----------------
#define N0C 120000
#define N1C 30000
#define N2C 6000
#define E0C 480000
#define E1C 96000
#define DC  128
#define RC  8
#define NBC 4
#define KNODE (DC + RC*DC)   // 1152
#define CAP  128
#define OVF_MAX 4096

// ---------------- device scratch ----------------
__device__ __half g_h0h[(size_t)N0C * DC];
__device__ __half g_acc0h[(size_t)N1C * RC * DC];
__device__ __half g_h1h[(size_t)N1C * DC];
__device__ __half g_acc1h[(size_t)N2C * RC * DC];
__device__ __half g_h2h[(size_t)N2C * DC];

__device__ int g_cnt0[N1C];
__device__ int g_cnt1[N2C];
__device__ unsigned int g_pay0[(size_t)N1C * CAP];
__device__ unsigned int g_pay1[(size_t)N2C * CAP];
__device__ int g_ovfn0[1];
__device__ int g_ovfn1[1];
__device__ uint2 g_ovf0[OVF_MAX];
__device__ uint2 g_ovf1[OVF_MAX];

__device__ __half g_WPre_hi[DC * DC];
__device__ __half g_WPre_lo[DC * DC];
__device__ __half g_W0_hi[KNODE * DC];
__device__ __half g_W0_lo[KNODE * DC];
__device__ __half g_W1_hi[KNODE * DC];
__device__ __half g_W1_lo[KNODE * DC];
__device__ __half g_WPost_hi[DC * DC];
__device__ __half g_WPost_lo[DC * DC];

// ---------------- helpers ----------------
__device__ __forceinline__ uint32_t smem_u32(const void* p) {
    uint32_t a;
    asm("{ .reg .u64 t; cvta.to.shared.u64 t, %1; cvt.u32.u64 %0, t; }" : "=r"(a) : "l"(p));
    return a;
}
__device__ __forceinline__ void cp16(uint32_t dst, const void* src, int sz) {
    asm volatile("cp.async.cg.shared.global [%0], [%1], 16, %2;"
                 :: "r"(dst), "l"(src), "r"(sz) : "memory");
}
__device__ __forceinline__ void cp_commit() {
    asm volatile("cp.async.commit_group;" ::: "memory");
}
template <int N>
__device__ __forceinline__ void cp_wait() {
    asm volatile("cp.async.wait_group %0;" :: "n"(N) : "memory");
}

// ---------------- fused setup: zero counters + fold/split all weights ----------------
#define SB_ZERO 118
#define SB_PRE  64
#define SB_POST 64
#define SB_NODE 576
#define SETUP_BLOCKS (SB_ZERO + SB_PRE + SB_POST + 2*SB_NODE)   // 1398

__device__ __forceinline__ void split_store(float v, __half* hi, __half* lo, int idx) {
    __half h = __float2half(v);
    hi[idx] = h;
    lo[idx] = __float2half(v - __half2float(h));
}

__device__ void build_node_W(int idx, const float* root, const float* basis,
                             const float* comp, __half* hi, __half* lo) {
    int k = idx >> 7, n = idx & 127;
    float v;
    if (k < DC) {
        v = root[k * DC + n];
    } else {
        int r = (k - DC) >> 7;
        int i = (k - DC) & 127;
        v = 0.f;
        #pragma unroll
        for (int b = 0; b < NBC; b++)
            v += comp[r * NBC + b] * basis[((size_t)b * DC + i) * DC + n];
    }
    split_store(v, hi, lo, idx);
}

__global__ void setup_kernel(const float* __restrict__ preW, const float* __restrict__ postW,
                             const float* __restrict__ root0, const float* __restrict__ basis0,
                             const float* __restrict__ comp0,
                             const float* __restrict__ root1, const float* __restrict__ basis1,
                             const float* __restrict__ comp1,
                             __half* preh, __half* prel, __half* posth, __half* postl,
                             __half* w0h, __half* w0l, __half* w1h, __half* w1l,
                             int* cnt0, int* cnt1, int* ovfn0, int* ovfn1) {
    int b = blockIdx.x;
    int t = threadIdx.x;
    if (b < SB_ZERO) {
        int i = b * 256 + t;
        if (i < N1C) cnt0[i] = 0;
        if (i < N2C) cnt1[i] = 0;
        if (i == 0) { ovfn0[0] = 0; ovfn1[0] = 0; }
    } else if (b < SB_ZERO + SB_PRE) {
        int idx = (b - SB_ZERO) * 256 + t;
        split_store(preW[idx], preh, prel, idx);
    } else if (b < SB_ZERO + SB_PRE + SB_POST) {
        int idx = (b - SB_ZERO - SB_PRE) * 256 + t;
        split_store(postW[idx], posth, postl, idx);
    } else if (b < SB_ZERO + SB_PRE + SB_POST + SB_NODE) {
        int idx = (b - SB_ZERO - SB_PRE - SB_POST) * 256 + t;
        build_node_W(idx, root0, basis0, comp0, w0h, w0l);
    } else {
        int idx = (b - SB_ZERO - SB_PRE - SB_POST - SB_NODE) * 256 + t;
        build_node_W(idx, root1, basis1, comp1, w1h, w1l);
    }
}

// ---------------- fused bucketing for both layers ----------------
#define NBK0 ((E0C + 255) / 256)
#define NBK1 ((E1C + 255) / 256)

__global__ void bucket_all(const int* __restrict__ src0, const int* __restrict__ dst0,
                           const int* __restrict__ eid0,
                           const int* __restrict__ src1, const int* __restrict__ dst1,
                           const int* __restrict__ eid1,
                           const int* __restrict__ et_all,
                           int* __restrict__ cnt0, unsigned int* __restrict__ pay0,
                           int* __restrict__ ovfn0, uint2* __restrict__ ovf0,
                           int* __restrict__ cnt1, unsigned int* __restrict__ pay1,
                           int* __restrict__ ovfn1, uint2* __restrict__ ovf1) {
    int b = blockIdx.x;
    const int* src; const int* dst; const int* eid;
    int* cnt; unsigned int* pay; int* ovfn; uint2* ovf;
    int e, E;
    if (b < NBK0) {
        e = b * 256 + threadIdx.x; E = E0C;
        src = src0; dst = dst0; eid = eid0;
        cnt = cnt0; pay = pay0; ovfn = ovfn0; ovf = ovf0;
    } else {
        e = (b - NBK0) * 256 + threadIdx.x; E = E1C;
        src = src1; dst = dst1; eid = eid1;
        cnt = cnt1; pay = pay1; ovfn = ovfn1; ovf = ovf1;
    }
    if (e >= E) return;
    int d = dst[e];
    unsigned int p = (unsigned int)src[e] | ((unsigned int)et_all[eid[e]] << 24);
    int i = atomicAdd(&cnt[d], 1);
    if (i < CAP) {
        pay[(size_t)d * CAP + i] = p;
    } else {
        int o = atomicAdd(ovfn, 1);
        if (o < OVF_MAX) ovf[o] = make_uint2(p, (unsigned int)d);
    }
}

// ---------------- gather-aggregate: warp per dst, payload prefetch + shfl ----------------
__global__ __launch_bounds__(256)
void gather_kernel(const int* __restrict__ cnt, const unsigned int* __restrict__ pay,
                   const __half* __restrict__ h, __half* __restrict__ acc, int N) {
    int d = blockIdx.x * 8 + (threadIdx.x >> 5);
    int lane = threadIdx.x & 31;
    if (d >= N) return;
    int ntot = cnt[d];
    int n = min(ntot, CAP);

    const unsigned int* pl = pay + (size_t)d * CAP;
    unsigned int myp[4];
    #pragma unroll
    for (int q = 0; q < 4; q++)
        myp[q] = (q * 32 + lane < n) ? __ldg(pl + q * 32 + lane) : 0u;

    float a[RC][4];
    #pragma unroll
    for (int r = 0; r < RC; r++)
        #pragma unroll
        for (int q = 0; q < 4; q++) a[r][q] = 0.f;

    for (int j = 0; j < n; j++) {
        unsigned int p = __shfl_sync(0xffffffffu, myp[j >> 5], j & 31);
        int s = (int)(p & 0xFFFFFFu);
        int et = (int)(p >> 24);
        uint2 u = *reinterpret_cast<const uint2*>(h + (size_t)s * DC + lane * 4);
        float2 f0 = __half22float2(*(__half2*)&u.x);
        float2 f1 = __half22float2(*(__half2*)&u.y);
        #pragma unroll
        for (int r = 0; r < RC; r++) {
            if (et == r) {
                a[r][0] += f0.x; a[r][1] += f0.y; a[r][2] += f1.x; a[r][3] += f1.y;
            }
        }
    }
    float inv = 1.0f / fmaxf((float)ntot, 1.0f);
    __half* out = acc + (size_t)d * (RC * DC) + lane * 4;
    #pragma unroll
    for (int r = 0; r < RC; r++) {
        __half2 o0 = __floats2half2_rn(a[r][0] * inv, a[r][1] * inv);
        __half2 o1 = __floats2half2_rn(a[r][2] * inv, a[r][3] * inv);
        uint2 o;
        o.x = *(uint32_t*)&o0; o.y = *(uint32_t*)&o1;
        *reinterpret_cast<uint2*>(out + r * DC) = o;
    }
}

// ---------------- overflow fixup (normally 0 work) ----------------
__global__ void ovf_fix_kernel(const int* __restrict__ ovfn, const uint2* __restrict__ ovf,
                               const int* __restrict__ cnt,
                               const __half* __restrict__ h, __half* __restrict__ acc) {
    int n = min(ovfn[0], OVF_MAX);
    int w = threadIdx.x >> 5;
    int lane = threadIdx.x & 31;
    for (int k = w; k < n; k += 8) {
        uint2 pr = ovf[k];
        int s = (int)(pr.x & 0xFFFFFFu);
        int et = (int)(pr.x >> 24);
        int d = (int)pr.y;
        float inv = 1.0f / fmaxf((float)cnt[d], 1.0f);
        __half2 iv = __float2half2_rn(inv);
        uint2 u = *reinterpret_cast<const uint2*>(h + (size_t)s * DC + lane * 4);
        __half2 p0 = __hmul2(*(__half2*)&u.x, iv);
        __half2 p1 = __hmul2(*(__half2*)&u.y, iv);
        __half2* a = (__half2*)(acc + (size_t)d * (RC * DC) + et * DC + lane * 4);
        atomicAdd(a + 0, p0);
        atomicAdd(a + 1, p1);
    }
}

// ================= GEMM kernels =================
enum { MODE_PRE = 0, MODE_NODE = 1, MODE_POST = 2 };
#define LDCS 132

// ---- shared epilogue (bias [+LN] [+relu], writes fp16 or fp32) ----
template <int MODE>
__device__ __forceinline__ void epilogue(char* smem, int offC, const float* s_bias,
                                         const float* s_g, const float* s_be,
                                         __half* outH, float* outF, int mBase, int M, int t) {
    const float* Cs = (const float*)(smem + offC);
    int row = t >> 1;
    int half = t & 1;
    int grow = mBase + row;
    const float* crow = Cs + row * LDCS + half * 64;
    float v[64];
    #pragma unroll
    for (int q = 0; q < 16; q++) {
        float4 cv = *reinterpret_cast<const float4*>(crow + q * 4);
        v[q * 4 + 0] = cv.x + s_bias[half * 64 + q * 4 + 0];
        v[q * 4 + 1] = cv.y + s_bias[half * 64 + q * 4 + 1];
        v[q * 4 + 2] = cv.z + s_bias[half * 64 + q * 4 + 2];
        v[q * 4 + 3] = cv.w + s_bias[half * 64 + q * 4 + 3];
    }
    if (MODE == MODE_NODE) {
        float s1 = 0.f, s2 = 0.f;
        #pragma unroll
        for (int j = 0; j < 64; j++) { s1 += v[j]; s2 += v[j] * v[j]; }
        s1 += __shfl_xor_sync(0xffffffffu, s1, 1);
        s2 += __shfl_xor_sync(0xffffffffu, s2, 1);
        float mu = s1 * (1.f / 128.f);
        float var = s2 * (1.f / 128.f) - mu * mu;
        float rs = rsqrtf(var + 1e-5f);
        #pragma unroll
        for (int j = 0; j < 64; j++)
            v[j] = fmaxf((v[j] - mu) * rs * s_g[half * 64 + j] + s_be[half * 64 + j], 0.f);
    } else if (MODE == MODE_PRE) {
        #pragma unroll
        for (int j = 0; j < 64; j++) v[j] = fmaxf(v[j], 0.f);
    }
    if (grow < M) {
        if (MODE == MODE_POST) {
            #pragma unroll
            for (int q = 0; q < 16; q++) {
                float4 o = make_float4(v[q * 4], v[q * 4 + 1], v[q * 4 + 2], v[q * 4 + 3]);
                *reinterpret_cast<float4*>(outF + (size_t)grow * DC + half * 64 + q * 4) = o;
            }
        } else {
            #pragma unroll
            for (int q = 0; q < 8; q++) {
                __half2 h0 = __floats2half2_rn(v[q * 8 + 0], v[q * 8 + 1]);
                __half2 h1 = __floats2half2_rn(v[q * 8 + 2], v[q * 8 + 3]);
                __half2 h2 = __floats2half2_rn(v[q * 8 + 4], v[q * 8 + 5]);
                __half2 h3 = __floats2half2_rn(v[q * 8 + 6], v[q * 8 + 7]);
                uint4 o;
                o.x = *(uint32_t*)&h0; o.y = *(uint32_t*)&h1;
                o.z = *(uint32_t*)&h2; o.w = *(uint32_t*)&h3;
                *reinterpret_cast<uint4*>(outH + (size_t)grow * DC + half * 64 + q * 8) = o;
            }
        }
    }
}

// ---- K=128 single-stage GEMM (pre: fp32 A in-kernel convert; post: fp16 A) ----
#define LDK 136
#define K1_OFF_BIAS 0
#define K1_OFF_A    2048
#define K1_OFF_BH   (K1_OFF_A + 128*LDK*2)      // 36864
#define K1_OFF_BL   (K1_OFF_BH + 128*LDK*2)     // 71680
#define K1_SMEM     (K1_OFF_BL + 128*LDK*2)     // 106496
#define K1_OFF_C    K1_OFF_A

template <int MODE>
__global__ __launch_bounds__(256)
void gemm_k128(const float* __restrict__ A32,
               const __half* __restrict__ A16,
               const __half* __restrict__ Whi,
               const __half* __restrict__ Wlo,
               const float* __restrict__ bias,
               __half* __restrict__ outH,
               float* __restrict__ outF,
               int M) {
    extern __shared__ char smem[];
    const uint32_t sb = smem_u32(smem);
    const int t = threadIdx.x;
    const int w = t >> 5;
    const int wm = w >> 1;
    const int wn = w & 1;
    const int mBase = blockIdx.x * 128;

    float* s_bias = (float*)(smem + K1_OFF_BIAS);
    if (t < 128) s_bias[t] = bias[t];

    __half* As = (__half*)(smem + K1_OFF_A);
    __half* Bh = (__half*)(smem + K1_OFF_BH);
    __half* Bl = (__half*)(smem + K1_OFF_BL);

    // B: full 128x128 hi+lo via cp.async (128 rows x 16 chunks of 16B each)
    #pragma unroll
    for (int it = 0; it < 8; it++) {
        int v = it * 256 + t;
        int row = v >> 4, seg = v & 15;
        uint32_t off = row * (LDK * 2) + seg * 16;
        cp16(sb + K1_OFF_BH + off, Whi + (size_t)row * DC + seg * 8, 16);
        cp16(sb + K1_OFF_BL + off, Wlo + (size_t)row * DC + seg * 8, 16);
    }
    cp_commit();

    // A: 128 rows x 128 cols  (FULL row: 32 float4 segs / 16 cp16 chunks)
    if (MODE == MODE_PRE) {
        #pragma unroll
        for (int it = 0; it < 16; it++) {
            int v = it * 256 + t;            // 4096 float4
            int row = v >> 5, seg = v & 31;
            int g = mBase + row;
            float4 av = make_float4(0.f, 0.f, 0.f, 0.f);
            if (g < M) av = *reinterpret_cast<const float4*>(A32 + (size_t)g * DC + seg * 4);
            __half2 p0 = __floats2half2_rn(av.x, av.y);
            __half2 p1 = __floats2half2_rn(av.z, av.w);
            uint2 o;
            o.x = *(uint32_t*)&p0; o.y = *(uint32_t*)&p1;
            *reinterpret_cast<uint2*>(As + row * LDK + seg * 4) = o;
        }
    } else {
        #pragma unroll
        for (int it = 0; it < 8; it++) {
            int v = it * 256 + t;            // 2048 cp16
            int row = v >> 4, seg = v & 15;
            int g = mBase + row;
            bool ok = g < M;
            cp16(sb + K1_OFF_A + row * (LDK * 2) + seg * 16,
                 A16 + (size_t)(ok ? g : 0) * DC + seg * 8, ok ? 16 : 0);
        }
        cp_commit();
    }
    cp_wait<0>();
    __syncthreads();

    wmma::fragment<wmma::accumulator, 16, 16, 16, float> acc[2][4];
    #pragma unroll
    for (int i = 0; i < 2; i++)
        #pragma unroll
        for (int j = 0; j < 4; j++)
            wmma::fill_fragment(acc[i][j], 0.f);

    #pragma unroll
    for (int ks = 0; ks < 8; ks++) {
        wmma::fragment<wmma::matrix_a, 16, 16, 16, __half, wmma::row_major> a[2];
        #pragma unroll
        for (int i = 0; i < 2; i++)
            wmma::load_matrix_sync(a[i], As + (wm * 32 + i * 16) * LDK + ks * 16, LDK);
        #pragma unroll
        for (int j = 0; j < 4; j++) {
            wmma::fragment<wmma::matrix_b, 16, 16, 16, __half, wmma::row_major> bh, bl;
            wmma::load_matrix_sync(bh, Bh + (ks * 16) * LDK + wn * 64 + j * 16, LDK);
            wmma::load_matrix_sync(bl, Bl + (ks * 16) * LDK + wn * 64 + j * 16, LDK);
            #pragma unroll
            for (int i = 0; i < 2; i++) {
                wmma::mma_sync(acc[i][j], a[i], bh, acc[i][j]);
                wmma::mma_sync(acc[i][j], a[i], bl, acc[i][j]);
            }
        }
    }

    __syncthreads();
    float* Cs = (float*)(smem + K1_OFF_C);
    #pragma unroll
    for (int i = 0; i < 2; i++)
        #pragma unroll
        for (int j = 0; j < 4; j++)
            wmma::store_matrix_sync(Cs + (wm * 32 + i * 16) * LDCS + wn * 64 + j * 16,
                                    acc[i][j], LDCS, wmma::mem_row_major);
    __syncthreads();
    epilogue<MODE>(smem, K1_OFF_C, s_bias, nullptr, nullptr, outH, outF, mBase, M, t);
}

// ---- K=1152 pipelined node GEMM (unchanged proven core) ----
#define LDA 72
#define LDB 136
#define A_BUF 18432
#define B_BUF 34816
#define OFF_BIAS 0
#define OFF_G    512
#define OFF_BE   1024
#define OFF_A    2048
#define OFF_B    (OFF_A + 2*A_BUF)
#define SMEM_TOT (OFF_B + 2*B_BUF)   // 108544
#define OFF_C    OFF_A

__global__ __launch_bounds__(256, 2)
void gemm_node(const __half* __restrict__ A,
               const __half* __restrict__ ACC,
               const __half* __restrict__ Whi,
               const __half* __restrict__ Wlo,
               const float* __restrict__ bias,
               const float* __restrict__ gamma,
               const float* __restrict__ beta,
               __half* __restrict__ outH,
               int M) {
    extern __shared__ char smem[];
    const uint32_t sb = smem_u32(smem);
    const int t = threadIdx.x;
    const int w = t >> 5;
    const int wm = w >> 1;
    const int wn = w & 1;
    const int mBase = blockIdx.x * 128;
    const int K = KNODE;

    float* s_bias = (float*)(smem + OFF_BIAS);
    float* s_g    = (float*)(smem + OFF_G);
    float* s_be   = (float*)(smem + OFF_BE);
    if (t < 128) { s_bias[t] = bias[t]; s_g[t] = gamma[t]; s_be[t] = beta[t]; }

    wmma::fragment<wmma::accumulator, 16, 16, 16, float> acc[2][4];
    #pragma unroll
    for (int i = 0; i < 2; i++)
        #pragma unroll
        for (int j = 0; j < 4; j++)
            wmma::fill_fragment(acc[i][j], 0.f);

    const int nCh = K >> 6;

    auto issue = [&](int c) {
        int buf = c & 1;
        int k0 = c * 64;
        #pragma unroll
        for (int it = 0; it < 4; it++) {
            int v = it * 256 + t;
            int row = v >> 3, seg = v & 7;
            int g = mBase + row;
            bool ok = g < M;
            const __half* src;
            if (k0 >= DC)
                src = ACC + (size_t)(ok ? g : 0) * (RC * DC) + (k0 - DC) + seg * 8;
            else
                src = A + (size_t)(ok ? g : 0) * DC + k0 + seg * 8;
            cp16(sb + OFF_A + buf * A_BUF + row * (LDA * 2) + seg * 16, src, ok ? 16 : 0);
        }
        #pragma unroll
        for (int it = 0; it < 4; it++) {
            int v = it * 256 + t;
            int row = v >> 4, seg = v & 15;
            uint32_t d0 = sb + OFF_B + buf * B_BUF + row * (LDB * 2) + seg * 16;
            cp16(d0, Whi + (size_t)(k0 + row) * DC + seg * 8, 16);
            cp16(d0 + 64 * (LDB * 2), Wlo + (size_t)(k0 + row) * DC + seg * 8, 16);
        }
    };

    issue(0);
    cp_commit();

    for (int c = 0; c < nCh; c++) {
        if (c + 1 < nCh) {
            issue(c + 1);
            cp_commit();
            cp_wait<1>();
        } else {
            cp_wait<0>();
        }
        __syncthreads();

        int buf = c & 1;
        const __half* As = (const __half*)(smem + OFF_A + buf * A_BUF);
        const __half* Bh = (const __half*)(smem + OFF_B + buf * B_BUF);
        const __half* Bl = Bh + 64 * LDB;

        #pragma unroll
        for (int ks = 0; ks < 4; ks++) {
            wmma::fragment<wmma::matrix_a, 16, 16, 16, __half, wmma::row_major> a[2];
            #pragma unroll
            for (int i = 0; i < 2; i++)
                wmma::load_matrix_sync(a[i], As + (wm * 32 + i * 16) * LDA + ks * 16, LDA);
            #pragma unroll
            for (int j = 0; j < 4; j++) {
                wmma::fragment<wmma::matrix_b, 16, 16, 16, __half, wmma::row_major> bh, bl;
                wmma::load_matrix_sync(bh, Bh + (ks * 16) * LDB + wn * 64 + j * 16, LDB);
                wmma::load_matrix_sync(bl, Bl + (ks * 16) * LDB + wn * 64 + j * 16, LDB);
                #pragma unroll
                for (int i = 0; i < 2; i++) {
                    wmma::mma_sync(acc[i][j], a[i], bh, acc[i][j]);
                    wmma::mma_sync(acc[i][j], a[i], bl, acc[i][j]);
                }
            }
        }
        __syncthreads();
    }

    float* Cs = (float*)(smem + OFF_C);
    #pragma unroll
    for (int i = 0; i < 2; i++)
        #pragma unroll
        for (int j = 0; j < 4; j++)
            wmma::store_matrix_sync(Cs + (wm * 32 + i * 16) * LDCS + wn * 64 + j * 16,
                                    acc[i][j], LDCS, wmma::mem_row_major);
    __syncthreads();
    epilogue<MODE_NODE>(smem, OFF_C, s_bias, s_g, s_be, outH, nullptr, mBase, M, t);
}

// ---------------- launch ----------------
extern "C" void kernel_launch(void* const* d_in, const int* in_sizes, int n_in,
                              void* d_out, int out_size) {
    const float* x     = (const float*)d_in[0];
    const int*   src0  = (const int*)d_in[1];
    const int*   dst0  = (const int*)d_in[2];
    const int*   eid0  = (const int*)d_in[3];
    const int*   src1  = (const int*)d_in[4];
    const int*   dst1  = (const int*)d_in[5];
    const int*   eid1  = (const int*)d_in[6];
    const int*   etall = (const int*)d_in[7];
    const float* preW  = (const float*)d_in[8];
    const float* preB  = (const float*)d_in[9];
    const float* basis0= (const float*)d_in[10];
    const float* comp0 = (const float*)d_in[11];
    const float* root0 = (const float*)d_in[12];
    const float* bias0 = (const float*)d_in[13];
    const float* g0    = (const float*)d_in[14];
    const float* be0   = (const float*)d_in[15];
    const float* basis1= (const float*)d_in[16];
    const float* comp1 = (const float*)d_in[17];
    const float* root1 = (const float*)d_in[18];
    const float* bias1 = (const float*)d_in[19];
    const float* g1    = (const float*)d_in[20];
    const float* be1   = (const float*)d_in[21];
    const float* postW = (const float*)d_in[22];
    const float* postB = (const float*)d_in[23];

    __half *h0h, *acc0h, *h1h, *acc1h, *h2h;
    int *cnt0, *cnt1, *ovfn0, *ovfn1;
    unsigned int *pay0, *pay1;
    uint2 *ovf0, *ovf1;
    __half *wpreh, *wprel, *w0h, *w0l, *w1h, *w1l, *wposth, *wpostl;
    cudaGetSymbolAddress((void**)&h0h,   g_h0h);
    cudaGetSymbolAddress((void**)&acc0h, g_acc0h);
    cudaGetSymbolAddress((void**)&h1h,   g_h1h);
    cudaGetSymbolAddress((void**)&acc1h, g_acc1h);
    cudaGetSymbolAddress((void**)&h2h,   g_h2h);
    cudaGetSymbolAddress((void**)&cnt0,  g_cnt0);
    cudaGetSymbolAddress((void**)&cnt1,  g_cnt1);
    cudaGetSymbolAddress((void**)&pay0,  g_pay0);
    cudaGetSymbolAddress((void**)&pay1,  g_pay1);
    cudaGetSymbolAddress((void**)&ovfn0, g_ovfn0);
    cudaGetSymbolAddress((void**)&ovfn1, g_ovfn1);
    cudaGetSymbolAddress((void**)&ovf0,  g_ovf0);
    cudaGetSymbolAddress((void**)&ovf1,  g_ovf1);
    cudaGetSymbolAddress((void**)&wpreh, g_WPre_hi);
    cudaGetSymbolAddress((void**)&wprel, g_WPre_lo);
    cudaGetSymbolAddress((void**)&w0h,   g_W0_hi);
    cudaGetSymbolAddress((void**)&w0l,   g_W0_lo);
    cudaGetSymbolAddress((void**)&w1h,   g_W1_hi);
    cudaGetSymbolAddress((void**)&w1l,   g_W1_lo);
    cudaGetSymbolAddress((void**)&wposth, g_WPost_hi);
    cudaGetSymbolAddress((void**)&wpostl, g_WPost_lo);

    cudaFuncSetAttribute(gemm_k128<MODE_PRE>,  cudaFuncAttributeMaxDynamicSharedMemorySize, K1_SMEM);
    cudaFuncSetAttribute(gemm_k128<MODE_POST>, cudaFuncAttributeMaxDynamicSharedMemorySize, K1_SMEM);
    cudaFuncSetAttribute(gemm_node, cudaFuncAttributeMaxDynamicSharedMemorySize, SMEM_TOT);

    // 1: fused setup (zero counters + all weight folds)
    setup_kernel<<<SETUP_BLOCKS, 256>>>(preW, postW, root0, basis0, comp0,
                                        root1, basis1, comp1,
                                        wpreh, wprel, wposth, wpostl,
                                        w0h, w0l, w1h, w1l,
                                        cnt0, cnt1, ovfn0, ovfn1);
    // 2: fused bucketing
    bucket_all<<<NBK0 + NBK1, 256>>>(src0, dst0, eid0, src1, dst1, eid1, etall,
                                     cnt0, pay0, ovfn0, ovf0, cnt1, pay1, ovfn1, ovf1);
    // 3: pre-GEMM (fp32 x converted in-kernel)
    gemm_k128<MODE_PRE><<<(N0C + 127) / 128, 256, K1_SMEM>>>(
        x, nullptr, wpreh, wprel, preB, h0h, nullptr, N0C);
    // 4-5: gather layer 0 + fixup
    gather_kernel<<<(N1C + 7) / 8, 256>>>(cnt0, pay0, h0h, acc0h, N1C);
    ovf_fix_kernel<<<1, 256>>>(ovfn0, ovf0, cnt0, h0h, acc0h);
    // 6: node0 GEMM
    gemm_node<<<(N1C + 127) / 128, 256, SMEM_TOT>>>(
        h0h, acc0h, w0h, w0l, bias0, g0, be0, h1h, N1C);
    // 7-8: gather layer 1 + fixup
    gather_kernel<<<(N2C + 7) / 8, 256>>>(cnt1, pay1, h1h, acc1h, N2C);
    ovf_fix_kernel<<<1, 256>>>(ovfn1, ovf1, cnt1, h1h, acc1h);
    // 9: node1 GEMM
    gemm_node<<<(N2C + 127) / 128, 256, SMEM_TOT>>>(
        h1h, acc1h, w1h, w1l, bias1, g1, be1, h2h, N2C);
    // 10: post GEMM -> fp32 out
    gemm_k128<MODE_POST><<<(N2C + 127) / 128, 256, K1_SMEM>>>(
        nullptr, h2h, wposth, wpostl, postB, nullptr, (float*)d_out, N2C);
}